// round 6
// baseline (speedup 1.0000x reference)
#include <cuda_runtime.h>
#include <cstdint>
#include <cstddef>

// ---------------- device scratch (static, no runtime alloc) ----------------
__device__ float g_preF[(size_t)1024 * 64 * 2048];      // x@Wf[:512]+bf, time-major [t][b][g]
__device__ float g_preB[(size_t)1024 * 64 * 2048];      // x@Wb[:512]+bb
__device__ float g_base[2][256][2048];                  // embed@W[:512] per vocab entry
__device__ uint2 g_dropPack[(size_t)65536 * 128];       // per row: (d, bits(e[tok][d])) dropped entries
__device__ unsigned int g_dropN[65536];                 // per row: dropped count
__device__ unsigned char g_zb[(size_t)2 * 1024 * 32768];// zoneout bits: bit0=keep h, bit1=keep c
__device__ uint2 g_kz[2 * 1024];                        // per-step zoneout keys (fwd, bwd)
__device__ uint2 g_kd;                                  // dropout key
__device__ float g_h[2][2][64 * 512];                   // [dir][parity][b*512+d]
__device__ unsigned int g_ctr[2];                       // per-direction step barrier

// ---------------- JAX threefry2x32 (bit-exact, 20 rounds) ----------------
__device__ __forceinline__ uint32_t rotl32(uint32_t x, int r) { return (x << r) | (x >> (32 - r)); }

__device__ __forceinline__ void tf2x32(uint32_t k0, uint32_t k1, uint32_t& x0, uint32_t& x1) {
    uint32_t k2 = k0 ^ k1 ^ 0x1BD11BDAu;
    x0 += k0; x1 += k1;
#define TFR(r) { x0 += x1; x1 = rotl32(x1, r); x1 ^= x0; }
    TFR(13) TFR(15) TFR(26) TFR(6)   x0 += k1; x1 += k2 + 1u;
    TFR(17) TFR(29) TFR(16) TFR(24)  x0 += k2; x1 += k0 + 2u;
    TFR(13) TFR(15) TFR(26) TFR(6)   x0 += k0; x1 += k1 + 3u;
    TFR(17) TFR(29) TFR(16) TFR(24)  x0 += k1; x1 += k2 + 4u;
    TFR(13) TFR(15) TFR(26) TFR(6)   x0 += k2; x1 += k0 + 5u;
#undef TFR
}

// partitionable random_bits (32-bit): element i -> tf(key, (0, i)), bits = x0 ^ x1
__device__ __forceinline__ uint32_t pbits(uint32_t k0, uint32_t k1, uint32_t i) {
    uint32_t x0 = 0u, x1 = i;
    tf2x32(k0, k1, x0, x1);
    return x0 ^ x1;
}

__device__ __forceinline__ float u01(uint32_t bits) {
    return __uint_as_float((bits >> 9) | 0x3f800000u) - 1.0f;
}
__device__ __forceinline__ float sigm(float x) { return 1.0f / (1.0f + expf(-x)); }

// ---------------- K1: key derivation (fold-like split) + barrier reset ----------------
__global__ void rng_setup_kernel() {
    int tid = threadIdx.x;
    __shared__ uint32_t s[4];
    if (tid == 0) {
        g_ctr[0] = 0u; g_ctr[1] = 0u;
        uint32_t a, b;
        a = 0u; b = 0u; tf2x32(0u, 42u, a, b); g_kd = make_uint2(a, b);
        a = 0u; b = 1u; tf2x32(0u, 42u, a, b); s[0] = a; s[1] = b;   // kf
        a = 0u; b = 2u; tf2x32(0u, 42u, a, b); s[2] = a; s[3] = b;   // kb
    }
    __syncthreads();
    if (tid < 2) {
        uint32_t k0 = s[tid * 2], k1 = s[tid * 2 + 1];
        for (int t = 0; t < 1024; ++t) {
            uint32_t z0 = 0u, z1 = 0u; tf2x32(k0, k1, z0, z1);
            uint32_t n0 = 0u, n1 = 1u; tf2x32(k0, k1, n0, n1);
            g_kz[tid * 1024 + t] = make_uint2(z0, z1);
            k0 = n0; k1 = n1;
        }
    }
}

// ---------------- K2: vocab base table: base[dir][v][g] = embed[v] . W[:512][g] ----------------
__global__ void __launch_bounds__(256) base_kernel(const float* __restrict__ embed,
                                                   const float* __restrict__ Wf,
                                                   const float* __restrict__ Wb) {
    int dir = blockIdx.z;
    const float* W = dir ? Wb : Wf;
    int g = blockIdx.x * 256 + threadIdx.x;
    int v0 = blockIdx.y * 4;
    float acc0 = 0.f, acc1 = 0.f, acc2 = 0.f, acc3 = 0.f;
#pragma unroll 4
    for (int d = 0; d < 512; ++d) {
        float w = W[(size_t)d * 2048 + g];
        acc0 = fmaf(embed[(size_t)(v0 + 0) * 512 + d], w, acc0);
        acc1 = fmaf(embed[(size_t)(v0 + 1) * 512 + d], w, acc1);
        acc2 = fmaf(embed[(size_t)(v0 + 2) * 512 + d], w, acc2);
        acc3 = fmaf(embed[(size_t)(v0 + 3) * 512 + d], w, acc3);
    }
    g_base[dir][v0 + 0][g] = acc0;
    g_base[dir][v0 + 1][g] = acc1;
    g_base[dir][v0 + 2][g] = acc2;
    g_base[dir][v0 + 3][g] = acc3;
}

// ---------------- K3: dropout -> compact per-row dropped (d, e) lists ----------------
__global__ void __launch_bounds__(256) drop_kernel(const int* __restrict__ tokens,
                                                   const float* __restrict__ embed) {
    unsigned row = (blockIdx.x * 256u + threadIdx.x) >> 5;   // [0, 65536)
    int lane = threadIdx.x & 31;
    uint2 kd = g_kd;
    int tok = tokens[row];
    const float* erow = &embed[(size_t)tok * 512];
    uint2* outp = &g_dropPack[(size_t)row * 128];
    unsigned count = 0;
#pragma unroll 4
    for (int it = 0; it < 16; ++it) {
        int d = it * 32 + lane;
        uint32_t bits = pbits(kd.x, kd.y, row * 512u + (unsigned)d);
        bool dropped = !(u01(bits) < 0.9f);
        unsigned m = __ballot_sync(0xffffffffu, dropped);
        if (dropped) {
            unsigned pos = count + __popc(m & ((1u << lane) - 1u));
            outp[pos] = make_uint2((unsigned)d, __float_as_uint(erow[d]));
        }
        count += __popc(m);
    }
    if (lane == 0) g_dropN[row] = count;
}

// ---------------- K4: zoneout mask precompute ----------------
__global__ void zoneout_kernel() {
    size_t gi = (size_t)blockIdx.x * 256 + threadIdx.x;    // [0, 2*1024*32768)
    unsigned pair = (unsigned)(gi & 32767u);
    unsigned st = (unsigned)(gi >> 15);                    // dir*1024 + s
    uint2 k = g_kz[st];
    uint32_t bh = pbits(k.x, k.y, pair);
    uint32_t bc = pbits(k.x, k.y, pair + 32768u);
    g_zb[gi] = (unsigned char)(((u01(bh) < 0.1f) ? 1u : 0u) | ((u01(bc) < 0.1f) ? 2u : 0u));
}

// ---------------- K5: projection via base table + sparse dropout correction ----------------
// pre[t][b][g] = (base[tok] - sum_dropped e_d * W[d][g]) / 0.9 + bias[g]
#define CORR_SMEM (512 * 64 * 4)

__global__ void __launch_bounds__(256, 1) proj_corr_kernel(const int* __restrict__ tokens,
                                                           const float* __restrict__ Wf,
                                                           const float* __restrict__ Wb,
                                                           const float* __restrict__ bf,
                                                           const float* __restrict__ bb) {
    extern __shared__ float sW[];   // [512][64]
    int dir = blockIdx.x >> 5;
    int slice = blockIdx.x & 31;
    int g0 = slice * 64;
    const float* W = dir ? Wb : Wf;
    const float* bias = dir ? bb : bf;
    float* pre = dir ? g_preB : g_preF;
    const float* base = &g_base[dir][0][0];
    int tid = threadIdx.x;

    for (int i = tid; i < 512 * 64; i += 256)
        sW[i] = W[(size_t)(i >> 6) * 2048 + g0 + (i & 63)];
    __syncthreads();

    int lane = tid & 31, w = tid >> 5;
    float2 bv = *(const float2*)&bias[g0 + lane * 2];
    int rEnd = blockIdx.y * 32768 + 32768;
    for (int r = blockIdx.y * 32768 + w; r < rEnd; r += 8) {
        int tok = tokens[r];
        float2 acc = *(const float2*)&base[(size_t)tok * 2048 + g0 + lane * 2];
        unsigned n = g_dropN[r];
        const uint2* lst = &g_dropPack[(size_t)r * 128];
#pragma unroll 4
        for (unsigned j = 0; j < n; ++j) {
            uint2 e = lst[j];
            float val = __uint_as_float(e.y);
            float2 wv = *(const float2*)&sW[e.x * 64 + lane * 2];
            acc.x = fmaf(-val, wv.x, acc.x);
            acc.y = fmaf(-val, wv.y, acc.y);
        }
        int b = r >> 10, t = r & 1023;
        float2 o;
        o.x = fmaf(acc.x, (1.0f / 0.9f), bv.x);
        o.y = fmaf(acc.y, (1.0f / 0.9f), bv.y);
        *(float2*)&pre[(((size_t)t * 64) + b) * 2048 + g0 + lane * 2] = o;
    }
}

// ---------------- K6: persistent bidirectional LSTM scan (plain FFMA matvec) ----------------
#define SH_STRIDE 516
#define SCAN_SMEM ((32 * 512 + 64 * SH_STRIDE) * 4)

__global__ void __launch_bounds__(256, 1) scan_kernel(const int* __restrict__ lengths,
                                                      const float* __restrict__ Wf,
                                                      const float* __restrict__ Wb,
                                                      float* __restrict__ out) {
    extern __shared__ float smem[];
    float* sWT = smem;                 // 32*512
    float* sH = smem + 32 * 512;       // 64*516
    __shared__ int sLen[64];

    int dir = blockIdx.x >> 6, cta = blockIdx.x & 63, d0 = cta * 8;
    int tid = threadIdx.x;
    const float* W = dir ? Wb : Wf;

    for (int idx = tid; idx < 32 * 512; idx += 256) {
        int j = idx >> 9, k = idx & 511;
        sWT[idx] = W[(size_t)(512 + k) * 2048 + ((j >> 3) << 9) + d0 + (j & 7)];
    }
    if (tid < 64) sLen[tid] = lengths[tid];

    int q = tid >> 6, b = tid & 63;
    int dd = q * 2, d = d0 + dd;
    float c0r = 0.f, c1r = 0.f;
    volatile unsigned int* ctr = &g_ctr[dir];
    const float* pre = dir ? g_preB : g_preF;
    const unsigned char* zbase = &g_zb[(size_t)dir * 1024 * 32768];
    __syncthreads();

    for (int s = 0; s < 1024; ++s) {
        int tx = dir ? (1023 - s) : s;
        // ---- stage h (with bwd ResetCore) ----
        if (s == 0) {
            for (int i = tid * 4; i < 32768; i += 1024)
                *(float4*)&sH[(i >> 9) * SH_STRIDE + (i & 511)] = make_float4(0, 0, 0, 0);
        } else {
            const float* hg = g_h[dir][s & 1];
            for (int i = tid * 4; i < 32768; i += 1024) {
                int hb = i >> 9, hd = i & 511;
                float4 v = __ldcg((const float4*)&hg[i]);
                if (dir && (1023 - s) < sLen[hb] - 1) v = make_float4(0, 0, 0, 0);
                *(float4*)&sH[hb * SH_STRIDE + hd] = v;
            }
        }
        __syncthreads();

        // ---- prefetch x-projection + zoneout bits ----
        size_t prow = ((size_t)tx * 64 + b) * 2048 + (size_t)d;
        float2 pxi = *(const float2*)&pre[prow];
        float2 pxg = *(const float2*)&pre[prow + 512];
        float2 pxf = *(const float2*)&pre[prow + 1024];
        float2 pxo = *(const float2*)&pre[prow + 1536];
        const unsigned char* zp = &zbase[((size_t)s << 15) + b * 512 + d];
        unsigned char z0 = zp[0], z1 = zp[1];

        // ---- h @ W_h slice: 8 gate pre-activations (plain FFMA) ----
        float acc[8] = {};
        const float* hrow = &sH[b * SH_STRIDE];
#pragma unroll 2
        for (int k = 0; k < 512; k += 4) {
            float4 hv = *(const float4*)&hrow[k];
#pragma unroll
            for (int u = 0; u < 8; ++u) {
                const float4 w = *(const float4*)&sWT[((u >> 1) * 8 + dd + (u & 1)) * 512 + k];
                acc[u] = fmaf(hv.x, w.x, fmaf(hv.y, w.y, fmaf(hv.z, w.z, fmaf(hv.w, w.w, acc[u]))));
            }
        }

        // ---- gates + zoneout ----
        if (dir && (1023 - s) < sLen[b] - 1) { c0r = 0.f; c1r = 0.f; }
        float i0 = pxi.x + acc[0], i1 = pxi.y + acc[1];
        float gg0 = pxg.x + acc[2], gg1 = pxg.y + acc[3];
        float f0 = sigm(pxf.x + acc[4] + 1.f), f1 = sigm(pxf.y + acc[5] + 1.f);
        float o0 = sigm(pxo.x + acc[6]), o1 = sigm(pxo.y + acc[7]);
        float cn0 = f0 * c0r + sigm(i0) * tanhf(gg0);
        float cn1 = f1 * c1r + sigm(i1) * tanhf(gg1);
        float hn0 = o0 * tanhf(cn0);
        float hn1 = o1 * tanhf(cn1);
        float hp0 = hrow[d], hp1 = hrow[d + 1];
        float ho0 = (z0 & 1) ? hp0 : hn0;
        float ho1 = (z1 & 1) ? hp1 : hn1;
        c0r = (z0 & 2) ? c0r : cn0;
        c1r = (z1 & 2) ? c1r : cn1;

        // ---- write h (for next step) + output ----
        float* hw = g_h[dir][(s + 1) & 1];
        float2 hv2 = make_float2(ho0, ho1);
        __stcg((float2*)&hw[b * 512 + d], hv2);
        *(float2*)&out[(((size_t)b << 10) + tx) * 1024 + ((size_t)dir << 9) + d] = hv2;

        // ---- per-direction grid barrier ----
        __syncthreads();
        if (s < 1023) {
            if (tid == 0) {
                __threadfence();
                atomicAdd((unsigned int*)ctr, 1u);
                unsigned int target = 64u * (unsigned)(s + 1);
                while (*ctr < target) { }
                __threadfence();
            }
            __syncthreads();
        }
    }
}

// ---------------- launch ----------------
extern "C" void kernel_launch(void* const* d_in, const int* in_sizes, int n_in,
                              void* d_out, int out_size) {
    (void)in_sizes; (void)n_in; (void)out_size;
    const int*   tokens  = (const int*)d_in[0];
    const int*   lengths = (const int*)d_in[1];
    const float* embed   = (const float*)d_in[2];
    const float* Wf      = (const float*)d_in[3];
    const float* bf      = (const float*)d_in[4];
    const float* Wb      = (const float*)d_in[5];
    const float* bb      = (const float*)d_in[6];
    float* out = (float*)d_out;

    cudaFuncSetAttribute(scan_kernel, cudaFuncAttributeMaxDynamicSharedMemorySize, SCAN_SMEM);
    cudaFuncSetAttribute(proj_corr_kernel, cudaFuncAttributeMaxDynamicSharedMemorySize, CORR_SMEM);

    rng_setup_kernel<<<1, 64>>>();
    base_kernel<<<dim3(8, 64, 2), 256>>>(embed, Wf, Wb);
    drop_kernel<<<8192, 256>>>(tokens, embed);
    zoneout_kernel<<<(2u * 1024u * 32768u) / 256u, 256>>>();
    proj_corr_kernel<<<dim3(64, 2), 256, CORR_SMEM>>>(tokens, Wf, Wb, bf, bb);
    scan_kernel<<<128, 256, SCAN_SMEM>>>(lengths, Wf, Wb, out);
}

// round 7
// speedup vs baseline: 1.5090x; 1.5090x over previous
#include <cuda_runtime.h>
#include <cstdint>
#include <cstddef>

// ---------------- device scratch (static, no runtime alloc) ----------------
__device__ float g_preF[(size_t)1024 * 64 * 2048];      // x@Wf[:512]+bf, time-major [t][b][g]
__device__ float g_preB[(size_t)1024 * 64 * 2048];      // x@Wb[:512]+bb
__device__ float g_base[2][256][2048];                  // embed@W[:512] per vocab entry
__device__ uint2 g_dropPack[(size_t)65536 * 128];       // per row: (d, bits(e[tok][d])) dropped entries
__device__ unsigned int g_dropN[65536];                 // per row: dropped count
__device__ unsigned char g_zb[(size_t)2 * 1024 * 32768];// zoneout bits: bit0=keep h, bit1=keep c
__device__ uint2 g_kz[2 * 1024];                        // per-step zoneout keys (fwd, bwd)
__device__ uint2 g_kd;                                  // dropout key
__device__ float g_h[2][2][64 * 512];                   // [dir][parity][b*512+d]
__device__ unsigned int g_ctr[2];                       // per-direction step barrier

// ---------------- JAX threefry2x32 (bit-exact, 20 rounds) ----------------
__device__ __forceinline__ uint32_t rotl32(uint32_t x, int r) { return (x << r) | (x >> (32 - r)); }

__device__ __forceinline__ void tf2x32(uint32_t k0, uint32_t k1, uint32_t& x0, uint32_t& x1) {
    uint32_t k2 = k0 ^ k1 ^ 0x1BD11BDAu;
    x0 += k0; x1 += k1;
#define TFR(r) { x0 += x1; x1 = rotl32(x1, r); x1 ^= x0; }
    TFR(13) TFR(15) TFR(26) TFR(6)   x0 += k1; x1 += k2 + 1u;
    TFR(17) TFR(29) TFR(16) TFR(24)  x0 += k2; x1 += k0 + 2u;
    TFR(13) TFR(15) TFR(26) TFR(6)   x0 += k0; x1 += k1 + 3u;
    TFR(17) TFR(29) TFR(16) TFR(24)  x0 += k1; x1 += k2 + 4u;
    TFR(13) TFR(15) TFR(26) TFR(6)   x0 += k2; x1 += k0 + 5u;
#undef TFR
}

// partitionable random_bits (32-bit): element i -> tf(key, (0, i)), bits = x0 ^ x1
__device__ __forceinline__ uint32_t pbits(uint32_t k0, uint32_t k1, uint32_t i) {
    uint32_t x0 = 0u, x1 = i;
    tf2x32(k0, k1, x0, x1);
    return x0 ^ x1;
}

__device__ __forceinline__ float u01(uint32_t bits) {
    return __uint_as_float((bits >> 9) | 0x3f800000u) - 1.0f;
}
__device__ __forceinline__ float sigm(float x) { return 1.0f / (1.0f + expf(-x)); }

// ---------------- K1: key derivation (fold-like split) + barrier reset ----------------
__global__ void rng_setup_kernel() {
    int tid = threadIdx.x;
    __shared__ uint32_t s[4];
    if (tid == 0) {
        g_ctr[0] = 0u; g_ctr[1] = 0u;
        uint32_t a, b;
        a = 0u; b = 0u; tf2x32(0u, 42u, a, b); g_kd = make_uint2(a, b);
        a = 0u; b = 1u; tf2x32(0u, 42u, a, b); s[0] = a; s[1] = b;   // kf
        a = 0u; b = 2u; tf2x32(0u, 42u, a, b); s[2] = a; s[3] = b;   // kb
    }
    __syncthreads();
    if (tid < 2) {
        uint32_t k0 = s[tid * 2], k1 = s[tid * 2 + 1];
        for (int t = 0; t < 1024; ++t) {
            uint32_t z0 = 0u, z1 = 0u; tf2x32(k0, k1, z0, z1);
            uint32_t n0 = 0u, n1 = 1u; tf2x32(k0, k1, n0, n1);
            g_kz[tid * 1024 + t] = make_uint2(z0, z1);
            k0 = n0; k1 = n1;
        }
    }
}

// ---------------- K2: vocab base table: base[dir][v][g] = embed[v] . W[:512][g] ----------------
__global__ void __launch_bounds__(256) base_kernel(const float* __restrict__ embed,
                                                   const float* __restrict__ Wf,
                                                   const float* __restrict__ Wb) {
    int dir = blockIdx.z;
    const float* W = dir ? Wb : Wf;
    int g = blockIdx.x * 256 + threadIdx.x;
    int v0 = blockIdx.y * 4;
    float acc0 = 0.f, acc1 = 0.f, acc2 = 0.f, acc3 = 0.f;
#pragma unroll 4
    for (int d = 0; d < 512; ++d) {
        float w = W[(size_t)d * 2048 + g];
        acc0 = fmaf(embed[(size_t)(v0 + 0) * 512 + d], w, acc0);
        acc1 = fmaf(embed[(size_t)(v0 + 1) * 512 + d], w, acc1);
        acc2 = fmaf(embed[(size_t)(v0 + 2) * 512 + d], w, acc2);
        acc3 = fmaf(embed[(size_t)(v0 + 3) * 512 + d], w, acc3);
    }
    g_base[dir][v0 + 0][g] = acc0;
    g_base[dir][v0 + 1][g] = acc1;
    g_base[dir][v0 + 2][g] = acc2;
    g_base[dir][v0 + 3][g] = acc3;
}

// ---------------- K3: dropout -> compact per-row dropped (d, e) lists ----------------
__global__ void __launch_bounds__(256) drop_kernel(const int* __restrict__ tokens,
                                                   const float* __restrict__ embed) {
    unsigned row = (blockIdx.x * 256u + threadIdx.x) >> 5;   // [0, 65536)
    int lane = threadIdx.x & 31;
    uint2 kd = g_kd;
    int tok = tokens[row];
    const float* erow = &embed[(size_t)tok * 512];
    uint2* outp = &g_dropPack[(size_t)row * 128];
    unsigned count = 0;
#pragma unroll 4
    for (int it = 0; it < 16; ++it) {
        int d = it * 32 + lane;
        uint32_t bits = pbits(kd.x, kd.y, row * 512u + (unsigned)d);
        bool dropped = !(u01(bits) < 0.9f);
        unsigned m = __ballot_sync(0xffffffffu, dropped);
        if (dropped) {
            unsigned pos = count + __popc(m & ((1u << lane) - 1u));
            outp[pos] = make_uint2((unsigned)d, __float_as_uint(erow[d]));
        }
        count += __popc(m);
    }
    if (lane == 0) g_dropN[row] = count;
}

// ---------------- K4: zoneout mask precompute ----------------
__global__ void zoneout_kernel() {
    size_t gi = (size_t)blockIdx.x * 256 + threadIdx.x;    // [0, 2*1024*32768)
    unsigned pair = (unsigned)(gi & 32767u);
    unsigned st = (unsigned)(gi >> 15);                    // dir*1024 + s
    uint2 k = g_kz[st];
    uint32_t bh = pbits(k.x, k.y, pair);
    uint32_t bc = pbits(k.x, k.y, pair + 32768u);
    g_zb[gi] = (unsigned char)(((u01(bh) < 0.1f) ? 1u : 0u) | ((u01(bc) < 0.1f) ? 2u : 0u));
}

// ---------------- K5: projection via base table + sparse dropout correction ----------------
// pre[t][b][g] = (base[tok] - sum_dropped e_d * W[d][g]) / 0.9 + bias[g]
#define CORR_SMEM (512 * 64 * 4)

__global__ void __launch_bounds__(256, 1) proj_corr_kernel(const int* __restrict__ tokens,
                                                           const float* __restrict__ Wf,
                                                           const float* __restrict__ Wb,
                                                           const float* __restrict__ bf,
                                                           const float* __restrict__ bb) {
    extern __shared__ float sW[];   // [512][64]
    int dir = blockIdx.x >> 5;
    int slice = blockIdx.x & 31;
    int g0 = slice * 64;
    const float* W = dir ? Wb : Wf;
    const float* bias = dir ? bb : bf;
    float* pre = dir ? g_preB : g_preF;
    const float* base = &g_base[dir][0][0];
    int tid = threadIdx.x;

    for (int i = tid; i < 512 * 64; i += 256)
        sW[i] = W[(size_t)(i >> 6) * 2048 + g0 + (i & 63)];
    __syncthreads();

    int lane = tid & 31, w = tid >> 5;
    float2 bv = *(const float2*)&bias[g0 + lane * 2];
    int rEnd = blockIdx.y * 32768 + 32768;
    for (int r = blockIdx.y * 32768 + w; r < rEnd; r += 8) {
        int tok = tokens[r];
        float2 acc = *(const float2*)&base[(size_t)tok * 2048 + g0 + lane * 2];
        unsigned n = g_dropN[r];
        const uint2* lst = &g_dropPack[(size_t)r * 128];
#pragma unroll 4
        for (unsigned j = 0; j < n; ++j) {
            uint2 e = lst[j];
            float val = __uint_as_float(e.y);
            float2 wv = *(const float2*)&sW[e.x * 64 + lane * 2];
            acc.x = fmaf(-val, wv.x, acc.x);
            acc.y = fmaf(-val, wv.y, acc.y);
        }
        int b = r >> 10, t = r & 1023;
        float2 o;
        o.x = fmaf(acc.x, (1.0f / 0.9f), bv.x);
        o.y = fmaf(acc.y, (1.0f / 0.9f), bv.y);
        *(float2*)&pre[(((size_t)t * 64) + b) * 2048 + g0 + lane * 2] = o;
    }
}

// ---------------- K6: persistent bidirectional LSTM scan (R4-identical) ----------------
#define SH_STRIDE 516
#define SCAN_SMEM ((32 * 512 + 64 * SH_STRIDE) * 4)

__global__ void __launch_bounds__(256, 1) scan_kernel(const int* __restrict__ lengths,
                                                      const float* __restrict__ Wf,
                                                      const float* __restrict__ Wb,
                                                      float* __restrict__ out) {
    extern __shared__ float smem[];
    float* sWT = smem;                 // 32*512
    float* sH = smem + 32 * 512;       // 64*516
    __shared__ int sLen[64];

    int dir = blockIdx.x >> 6, cta = blockIdx.x & 63, d0 = cta * 8;
    int tid = threadIdx.x;
    const float* W = dir ? Wb : Wf;

    for (int idx = tid; idx < 32 * 512; idx += 256) {
        int j = idx >> 9, k = idx & 511;
        sWT[idx] = W[(size_t)(512 + k) * 2048 + ((j >> 3) << 9) + d0 + (j & 7)];
    }
    if (tid < 64) sLen[tid] = lengths[tid];

    int q = tid >> 6, b = tid & 63;
    int dd = q * 2, d = d0 + dd;
    float c0r = 0.f, c1r = 0.f;
    volatile unsigned int* ctr = &g_ctr[dir];
    const float* pre = dir ? g_preB : g_preF;
    const unsigned char* zbase = &g_zb[(size_t)dir * 1024 * 32768];
    __syncthreads();

    for (int s = 0; s < 1024; ++s) {
        int tx = dir ? (1023 - s) : s;
        // ---- stage h (with bwd ResetCore) ----
        if (s == 0) {
            for (int i = tid * 4; i < 32768; i += 1024)
                *(float4*)&sH[(i >> 9) * SH_STRIDE + (i & 511)] = make_float4(0, 0, 0, 0);
        } else {
            const float* hg = g_h[dir][s & 1];
            for (int i = tid * 4; i < 32768; i += 1024) {
                int hb = i >> 9, hd = i & 511;
                float4 v = __ldcg((const float4*)&hg[i]);
                if (dir && (1023 - s) < sLen[hb] - 1) v = make_float4(0, 0, 0, 0);
                *(float4*)&sH[hb * SH_STRIDE + hd] = v;
            }
        }
        __syncthreads();

        // ---- prefetch x-projection + zoneout bits ----
        size_t prow = ((size_t)tx * 64 + b) * 2048 + (size_t)d;
        float2 pxi = *(const float2*)&pre[prow];
        float2 pxg = *(const float2*)&pre[prow + 512];
        float2 pxf = *(const float2*)&pre[prow + 1024];
        float2 pxo = *(const float2*)&pre[prow + 1536];
        const unsigned char* zp = &zbase[((size_t)s << 15) + b * 512 + d];
        unsigned char z0 = zp[0], z1 = zp[1];

        // ---- h @ W_h slice: 8 gate pre-activations (plain FFMA) ----
        float acc[8] = {};
        const float* hrow = &sH[b * SH_STRIDE];
#pragma unroll 2
        for (int k = 0; k < 512; k += 4) {
            float4 hv = *(const float4*)&hrow[k];
#pragma unroll
            for (int u = 0; u < 8; ++u) {
                const float4 w = *(const float4*)&sWT[((u >> 1) * 8 + dd + (u & 1)) * 512 + k];
                acc[u] = fmaf(hv.x, w.x, fmaf(hv.y, w.y, fmaf(hv.z, w.z, fmaf(hv.w, w.w, acc[u]))));
            }
        }

        // ---- gates + zoneout ----
        if (dir && (1023 - s) < sLen[b] - 1) { c0r = 0.f; c1r = 0.f; }
        float i0 = pxi.x + acc[0], i1 = pxi.y + acc[1];
        float gg0 = pxg.x + acc[2], gg1 = pxg.y + acc[3];
        float f0 = sigm(pxf.x + acc[4] + 1.f), f1 = sigm(pxf.y + acc[5] + 1.f);
        float o0 = sigm(pxo.x + acc[6]), o1 = sigm(pxo.y + acc[7]);
        float cn0 = f0 * c0r + sigm(i0) * tanhf(gg0);
        float cn1 = f1 * c1r + sigm(i1) * tanhf(gg1);
        float hn0 = o0 * tanhf(cn0);
        float hn1 = o1 * tanhf(cn1);
        float hp0 = hrow[d], hp1 = hrow[d + 1];
        float ho0 = (z0 & 1) ? hp0 : hn0;
        float ho1 = (z1 & 1) ? hp1 : hn1;
        c0r = (z0 & 2) ? c0r : cn0;
        c1r = (z1 & 2) ? c1r : cn1;

        // ---- write h (for next step) + output ----
        float* hw = g_h[dir][(s + 1) & 1];
        float2 hv2 = make_float2(ho0, ho1);
        __stcg((float2*)&hw[b * 512 + d], hv2);
        *(float2*)&out[(((size_t)b << 10) + tx) * 1024 + ((size_t)dir << 9) + d] = hv2;

        // ---- per-direction grid barrier (nanosleep-throttled poll) ----
        __syncthreads();
        if (s < 1023) {
            if (tid == 0) {
                __threadfence();
                atomicAdd((unsigned int*)ctr, 1u);
                unsigned int target = 64u * (unsigned)(s + 1);
                while (*ctr < target) __nanosleep(64);
                __threadfence();
            }
            __syncthreads();
        }
    }
}

// ---------------- launch ----------------
extern "C" void kernel_launch(void* const* d_in, const int* in_sizes, int n_in,
                              void* d_out, int out_size) {
    (void)in_sizes; (void)n_in; (void)out_size;
    const int*   tokens  = (const int*)d_in[0];
    const int*   lengths = (const int*)d_in[1];
    const float* embed   = (const float*)d_in[2];
    const float* Wf      = (const float*)d_in[3];
    const float* bf      = (const float*)d_in[4];
    const float* Wb      = (const float*)d_in[5];
    const float* bb      = (const float*)d_in[6];
    float* out = (float*)d_out;

    cudaFuncSetAttribute(scan_kernel, cudaFuncAttributeMaxDynamicSharedMemorySize, SCAN_SMEM);
    cudaFuncSetAttribute(proj_corr_kernel, cudaFuncAttributeMaxDynamicSharedMemorySize, CORR_SMEM);

    rng_setup_kernel<<<1, 64>>>();
    base_kernel<<<dim3(8, 64, 2), 256>>>(embed, Wf, Wb);
    drop_kernel<<<8192, 256>>>(tokens, embed);
    zoneout_kernel<<<(2u * 1024u * 32768u) / 256u, 256>>>();
    proj_corr_kernel<<<dim3(64, 2), 256, CORR_SMEM>>>(tokens, Wf, Wb, bf, bb);
    scan_kernel<<<128, 256, SCAN_SMEM>>>(lengths, Wf, Wb, out);
}

// round 8
// speedup vs baseline: 2.0870x; 1.3831x over previous
#include <cuda_runtime.h>
#include <cstdint>
#include <cstddef>

// ---------------- device scratch (static, no runtime alloc) ----------------
__device__ float g_preF[(size_t)1024 * 64 * 2048];      // x@Wf[:512]+bf, time-major [t][b][g]
__device__ float g_preB[(size_t)1024 * 64 * 2048];      // x@Wb[:512]+bb
__device__ float g_base[2][256][2048];                  // embed@W[:512] per vocab entry
__device__ uint2 g_dropPack[(size_t)65536 * 128];       // per row: (d, bits(e[tok][d])) dropped entries
__device__ unsigned int g_dropN[65536];                 // per row: dropped count
__device__ unsigned char g_zb[(size_t)2 * 1024 * 32768];// zoneout bits: bit0=keep h, bit1=keep c
__device__ uint2 g_kz[2 * 1024];                        // per-step zoneout keys (fwd, bwd)
__device__ uint2 g_kd;                                  // dropout key
// padded h exchange buffer: [dir][parity][b*516 + d] so one bulk copy lands bank-conflict-free
__device__ __align__(16) float g_h[2][2][64 * 516];
__device__ unsigned int g_ctr[2];                       // per-direction step barrier

// ---------------- JAX threefry2x32 (bit-exact, 20 rounds) ----------------
__device__ __forceinline__ uint32_t rotl32(uint32_t x, int r) { return (x << r) | (x >> (32 - r)); }

__device__ __forceinline__ void tf2x32(uint32_t k0, uint32_t k1, uint32_t& x0, uint32_t& x1) {
    uint32_t k2 = k0 ^ k1 ^ 0x1BD11BDAu;
    x0 += k0; x1 += k1;
#define TFR(r) { x0 += x1; x1 = rotl32(x1, r); x1 ^= x0; }
    TFR(13) TFR(15) TFR(26) TFR(6)   x0 += k1; x1 += k2 + 1u;
    TFR(17) TFR(29) TFR(16) TFR(24)  x0 += k2; x1 += k0 + 2u;
    TFR(13) TFR(15) TFR(26) TFR(6)   x0 += k0; x1 += k1 + 3u;
    TFR(17) TFR(29) TFR(16) TFR(24)  x0 += k1; x1 += k2 + 4u;
    TFR(13) TFR(15) TFR(26) TFR(6)   x0 += k2; x1 += k0 + 5u;
#undef TFR
}

__device__ __forceinline__ uint32_t pbits(uint32_t k0, uint32_t k1, uint32_t i) {
    uint32_t x0 = 0u, x1 = i;
    tf2x32(k0, k1, x0, x1);
    return x0 ^ x1;
}

__device__ __forceinline__ float u01(uint32_t bits) {
    return __uint_as_float((bits >> 9) | 0x3f800000u) - 1.0f;
}
__device__ __forceinline__ float sigm(float x) { return 1.0f / (1.0f + expf(-x)); }

// ---------------- K1: key derivation (fold-like split) + barrier reset ----------------
__global__ void rng_setup_kernel() {
    int tid = threadIdx.x;
    __shared__ uint32_t s[4];
    if (tid == 0) {
        g_ctr[0] = 0u; g_ctr[1] = 0u;
        uint32_t a, b;
        a = 0u; b = 0u; tf2x32(0u, 42u, a, b); g_kd = make_uint2(a, b);
        a = 0u; b = 1u; tf2x32(0u, 42u, a, b); s[0] = a; s[1] = b;   // kf
        a = 0u; b = 2u; tf2x32(0u, 42u, a, b); s[2] = a; s[3] = b;   // kb
    }
    __syncthreads();
    if (tid < 2) {
        uint32_t k0 = s[tid * 2], k1 = s[tid * 2 + 1];
        for (int t = 0; t < 1024; ++t) {
            uint32_t z0 = 0u, z1 = 0u; tf2x32(k0, k1, z0, z1);
            uint32_t n0 = 0u, n1 = 1u; tf2x32(k0, k1, n0, n1);
            g_kz[tid * 1024 + t] = make_uint2(z0, z1);
            k0 = n0; k1 = n1;
        }
    }
}

// ---------------- K2: vocab base table: base[dir][v][g] = embed[v] . W[:512][g] ----------------
__global__ void __launch_bounds__(256) base_kernel(const float* __restrict__ embed,
                                                   const float* __restrict__ Wf,
                                                   const float* __restrict__ Wb) {
    int dir = blockIdx.z;
    const float* W = dir ? Wb : Wf;
    int g = blockIdx.x * 256 + threadIdx.x;
    int v0 = blockIdx.y * 4;
    float acc0 = 0.f, acc1 = 0.f, acc2 = 0.f, acc3 = 0.f;
#pragma unroll 4
    for (int d = 0; d < 512; ++d) {
        float w = W[(size_t)d * 2048 + g];
        acc0 = fmaf(embed[(size_t)(v0 + 0) * 512 + d], w, acc0);
        acc1 = fmaf(embed[(size_t)(v0 + 1) * 512 + d], w, acc1);
        acc2 = fmaf(embed[(size_t)(v0 + 2) * 512 + d], w, acc2);
        acc3 = fmaf(embed[(size_t)(v0 + 3) * 512 + d], w, acc3);
    }
    g_base[dir][v0 + 0][g] = acc0;
    g_base[dir][v0 + 1][g] = acc1;
    g_base[dir][v0 + 2][g] = acc2;
    g_base[dir][v0 + 3][g] = acc3;
}

// ---------------- K3: dropout -> compact per-row dropped (d, e) lists ----------------
__global__ void __launch_bounds__(256) drop_kernel(const int* __restrict__ tokens,
                                                   const float* __restrict__ embed) {
    unsigned row = (blockIdx.x * 256u + threadIdx.x) >> 5;   // [0, 65536)
    int lane = threadIdx.x & 31;
    uint2 kd = g_kd;
    int tok = tokens[row];
    const float* erow = &embed[(size_t)tok * 512];
    uint2* outp = &g_dropPack[(size_t)row * 128];
    unsigned count = 0;
#pragma unroll 4
    for (int it = 0; it < 16; ++it) {
        int d = it * 32 + lane;
        uint32_t bits = pbits(kd.x, kd.y, row * 512u + (unsigned)d);
        bool dropped = !(u01(bits) < 0.9f);
        unsigned m = __ballot_sync(0xffffffffu, dropped);
        if (dropped) {
            unsigned pos = count + __popc(m & ((1u << lane) - 1u));
            outp[pos] = make_uint2((unsigned)d, __float_as_uint(erow[d]));
        }
        count += __popc(m);
    }
    if (lane == 0) g_dropN[row] = count;
}

// ---------------- K4: zoneout mask precompute ----------------
__global__ void zoneout_kernel() {
    size_t gi = (size_t)blockIdx.x * 256 + threadIdx.x;    // [0, 2*1024*32768)
    unsigned pair = (unsigned)(gi & 32767u);
    unsigned st = (unsigned)(gi >> 15);                    // dir*1024 + s
    uint2 k = g_kz[st];
    uint32_t bh = pbits(k.x, k.y, pair);
    uint32_t bc = pbits(k.x, k.y, pair + 32768u);
    g_zb[gi] = (unsigned char)(((u01(bh) < 0.1f) ? 1u : 0u) | ((u01(bc) < 0.1f) ? 2u : 0u));
}

// ---------------- K5: projection via base table + sparse dropout correction ----------------
// pre[t][b][g] = (base[tok] - sum_dropped e_d * W[d][g]) / 0.9 + bias[g]
// grid (64, 32): x = dir*32+slice, y = row-chunk of 2048 rows. Warp-coalesced
// list loads + shfl broadcast kill the serial-LDG latency chain.
#define CORR_SMEM (512 * 64 * 4)

__global__ void __launch_bounds__(256, 1) proj_corr_kernel(const int* __restrict__ tokens,
                                                           const float* __restrict__ Wf,
                                                           const float* __restrict__ Wb,
                                                           const float* __restrict__ bf,
                                                           const float* __restrict__ bb) {
    extern __shared__ float sW[];   // [512][64]
    int dir = blockIdx.x >> 5;
    int slice = blockIdx.x & 31;
    int g0 = slice * 64;
    const float* W = dir ? Wb : Wf;
    const float* bias = dir ? bb : bf;
    float* pre = dir ? g_preB : g_preF;
    const float* base = &g_base[dir][0][0];
    int tid = threadIdx.x;

    for (int i = tid; i < 512 * 64; i += 256)
        sW[i] = W[(size_t)(i >> 6) * 2048 + g0 + (i & 63)];
    __syncthreads();

    int lane = tid & 31, w = tid >> 5;
    float2 bv = *(const float2*)&bias[g0 + lane * 2];
    int rEnd = blockIdx.y * 2048 + 2048;
    for (int r = blockIdx.y * 2048 + w; r < rEnd; r += 8) {
        int tok = tokens[r];
        unsigned n = g_dropN[r];
        const uint2* lst = &g_dropPack[(size_t)r * 128];
        float2 acc = *(const float2*)&base[(size_t)tok * 2048 + g0 + lane * 2];
        for (unsigned j0 = 0; j0 < n; j0 += 32) {
            uint2 e = make_uint2(0u, 0u);
            if (j0 + lane < n) e = __ldcg(&lst[j0 + lane]);
            unsigned m = n - j0; if (m > 32u) m = 32u;
            for (unsigned jj = 0; jj < m; ++jj) {
                unsigned dx = __shfl_sync(0xffffffffu, e.x, jj);
                unsigned dv = __shfl_sync(0xffffffffu, e.y, jj);
                float val = __uint_as_float(dv);
                float2 wv = *(const float2*)&sW[dx * 64 + lane * 2];
                acc.x = fmaf(-val, wv.x, acc.x);
                acc.y = fmaf(-val, wv.y, acc.y);
            }
        }
        int b = r >> 10, t = r & 1023;
        float2 o;
        o.x = fmaf(acc.x, (1.0f / 0.9f), bv.x);
        o.y = fmaf(acc.y, (1.0f / 0.9f), bv.y);
        *(float2*)&pre[(((size_t)t * 64) + b) * 2048 + g0 + lane * 2] = o;
    }
}

// ---------------- K6: persistent bidirectional LSTM scan (TMA-staged h) ----------------
#define SH_STRIDE 516
#define H_BYTES (64 * SH_STRIDE * 4)             // 132096, %16 == 0
#define SCAN_SMEM ((32 * 512 + 64 * SH_STRIDE) * 4)

__global__ void __launch_bounds__(256, 1) scan_kernel(const int* __restrict__ lengths,
                                                      const float* __restrict__ Wf,
                                                      const float* __restrict__ Wb,
                                                      float* __restrict__ out) {
    extern __shared__ float smem[];
    float* sWT = smem;                 // 32*512
    float* sH = smem + 32 * 512;       // 64*516 (padded rows; TMA-bulk destination)
    __shared__ int sLen[64];
    __shared__ __align__(8) unsigned long long mbar;

    int dir = blockIdx.x >> 6, cta = blockIdx.x & 63, d0 = cta * 8;
    int tid = threadIdx.x;
    const float* W = dir ? Wb : Wf;

    unsigned mbar_u32 = (unsigned)__cvta_generic_to_shared(&mbar);
    unsigned sH_u32 = (unsigned)__cvta_generic_to_shared(sH);
    if (tid == 0)
        asm volatile("mbarrier.init.shared.b64 [%0], 1;" :: "r"(mbar_u32) : "memory");

    for (int idx = tid; idx < 32 * 512; idx += 256) {
        int j = idx >> 9, k = idx & 511;
        sWT[idx] = W[(size_t)(512 + k) * 2048 + ((j >> 3) << 9) + d0 + (j & 7)];
    }
    if (tid < 64) sLen[tid] = lengths[tid];

    int q = tid >> 6, b = tid & 63;
    int dd = q * 2, d = d0 + dd;
    float c0r = 0.f, c1r = 0.f;
    volatile unsigned int* ctr = &g_ctr[dir];
    const float* pre = dir ? g_preB : g_preF;
    const unsigned char* zbase = &g_zb[(size_t)dir * 1024 * 32768];
    __syncthreads();

    for (int s = 0; s < 1024; ++s) {
        int tx = dir ? (1023 - s) : s;

        // ---- stage h via one TMA bulk copy (g_h pre-zeroed for s=0; reset pre-applied by writers) ----
        if (tid == 0) {
            const float* src = g_h[dir][s & 1];
            asm volatile("mbarrier.arrive.expect_tx.shared.b64 _, [%0], %1;"
                         :: "r"(mbar_u32), "r"((unsigned)H_BYTES) : "memory");
            asm volatile("cp.async.bulk.shared::cta.global.mbarrier::complete_tx::bytes [%0], [%1], %2, [%3];"
                         :: "r"(sH_u32), "l"(src), "r"((unsigned)H_BYTES), "r"(mbar_u32) : "memory");
        }
        {
            unsigned p = (unsigned)(s & 1);
            asm volatile(
                "{\n\t"
                ".reg .pred P;\n\t"
                "WL_%=:\n\t"
                "mbarrier.try_wait.parity.acquire.cta.shared::cta.b64 P, [%0], %1, 0x989680;\n\t"
                "@P bra WD_%=;\n\t"
                "bra WL_%=;\n\t"
                "WD_%=:\n\t"
                "}"
                :: "r"(mbar_u32), "r"(p) : "memory");
        }

        // ---- prefetch x-projection + zoneout bits ----
        size_t prow = ((size_t)tx * 64 + b) * 2048 + (size_t)d;
        float2 pxi = *(const float2*)&pre[prow];
        float2 pxg = *(const float2*)&pre[prow + 512];
        float2 pxf = *(const float2*)&pre[prow + 1024];
        float2 pxo = *(const float2*)&pre[prow + 1536];
        const unsigned char* zp = &zbase[((size_t)s << 15) + b * 512 + d];
        unsigned char z0 = zp[0], z1 = zp[1];

        // ---- h @ W_h slice: 8 gate pre-activations (plain FFMA) ----
        float acc[8] = {};
        const float* hrow = &sH[b * SH_STRIDE];
#pragma unroll 2
        for (int k = 0; k < 512; k += 4) {
            float4 hv = *(const float4*)&hrow[k];
#pragma unroll
            for (int u = 0; u < 8; ++u) {
                const float4 w = *(const float4*)&sWT[((u >> 1) * 8 + dd + (u & 1)) * 512 + k];
                acc[u] = fmaf(hv.x, w.x, fmaf(hv.y, w.y, fmaf(hv.z, w.z, fmaf(hv.w, w.w, acc[u]))));
            }
        }

        // ---- gates + zoneout (c reset applied here; staged h already reset-applied) ----
        if (dir && (1023 - s) < sLen[b] - 1) { c0r = 0.f; c1r = 0.f; }
        float i0 = pxi.x + acc[0], i1 = pxi.y + acc[1];
        float gg0 = pxg.x + acc[2], gg1 = pxg.y + acc[3];
        float f0 = sigm(pxf.x + acc[4] + 1.f), f1 = sigm(pxf.y + acc[5] + 1.f);
        float o0 = sigm(pxo.x + acc[6]), o1 = sigm(pxo.y + acc[7]);
        float cn0 = f0 * c0r + sigm(i0) * tanhf(gg0);
        float cn1 = f1 * c1r + sigm(i1) * tanhf(gg1);
        float hn0 = o0 * tanhf(cn0);
        float hn1 = o1 * tanhf(cn1);
        float hp0 = hrow[d], hp1 = hrow[d + 1];
        float ho0 = (z0 & 1) ? hp0 : hn0;
        float ho1 = (z1 & 1) ? hp1 : hn1;
        c0r = (z0 & 2) ? c0r : cn0;
        c1r = (z1 & 2) ? c1r : cn1;

        // ---- output (unmasked), then h for next step with NEXT step's reset pre-applied ----
        float2 outv = make_float2(ho0, ho1);
        *(float2*)&out[(((size_t)b << 10) + tx) * 1024 + ((size_t)dir << 9) + d] = outv;

        float2 hv2 = outv;
        if (dir && (1022 - s) < sLen[b] - 1) hv2 = make_float2(0.f, 0.f);
        float* hw = g_h[dir][(s + 1) & 1];
        __stcg((float2*)&hw[b * SH_STRIDE + d], hv2);

        // ---- per-direction grid barrier (nanosleep-throttled poll) ----
        __syncthreads();
        if (s < 1023) {
            if (tid == 0) {
                __threadfence();
                atomicAdd((unsigned int*)ctr, 1u);
                unsigned int target = 64u * (unsigned)(s + 1);
                while (*ctr < target) __nanosleep(64);
                __threadfence();
            }
            __syncthreads();
        }
    }
}

// ---------------- launch ----------------
extern "C" void kernel_launch(void* const* d_in, const int* in_sizes, int n_in,
                              void* d_out, int out_size) {
    (void)in_sizes; (void)n_in; (void)out_size;
    const int*   tokens  = (const int*)d_in[0];
    const int*   lengths = (const int*)d_in[1];
    const float* embed   = (const float*)d_in[2];
    const float* Wf      = (const float*)d_in[3];
    const float* bf      = (const float*)d_in[4];
    const float* Wb      = (const float*)d_in[5];
    const float* bb      = (const float*)d_in[6];
    float* out = (float*)d_out;

    cudaFuncSetAttribute(scan_kernel, cudaFuncAttributeMaxDynamicSharedMemorySize, SCAN_SMEM);
    cudaFuncSetAttribute(proj_corr_kernel, cudaFuncAttributeMaxDynamicSharedMemorySize, CORR_SMEM);

    void* h_ptr = nullptr;
    cudaGetSymbolAddress(&h_ptr, g_h);

    rng_setup_kernel<<<1, 64>>>();
    base_kernel<<<dim3(8, 64, 2), 256>>>(embed, Wf, Wb);
    drop_kernel<<<8192, 256>>>(tokens, embed);
    zoneout_kernel<<<(2u * 1024u * 32768u) / 256u, 256>>>();
    cudaMemsetAsync(h_ptr, 0, sizeof(float) * 2 * 2 * 64 * SH_STRIDE);
    proj_corr_kernel<<<dim3(64, 32), 256, CORR_SMEM>>>(tokens, Wf, Wb, bf, bb);
    scan_kernel<<<128, 256, SCAN_SMEM>>>(lengths, Wf, Wb, out);
}

// round 10
// speedup vs baseline: 2.7854x; 1.3346x over previous
#include <cuda_runtime.h>
#include <cuda_bf16.h>
#include <mma.h>
#include <cstdint>
#include <cstddef>

using namespace nvcuda;

// ---------------- device scratch (static, no runtime alloc) ----------------
__device__ float g_preF[(size_t)1024 * 64 * 2048];      // x@Wf[:512]+bf, time-major [t][b][g]
__device__ float g_preB[(size_t)1024 * 64 * 2048];      // x@Wb[:512]+bb
__device__ float g_base[2][256][2048];                  // embed@W[:512] per vocab entry
__device__ uint2 g_dropPack[(size_t)65536 * 128];       // per row: (d, bits(e[tok][d])) dropped entries
__device__ unsigned int g_dropN[65536];                 // per row: dropped count
__device__ unsigned char g_zb[(size_t)2 * 1024 * 32768];// zoneout bits: bit0=keep h, bit1=keep c
__device__ uint2 g_kz[2 * 1024];                        // per-step zoneout keys (fwd, bwd)
__device__ uint2 g_kd;                                  // dropout key
// h exchange: A-tile byte image, rows 0-63 = h_hi (bf16), rows 64-127 = h_lo, ld=520 bf16
#define LDA 520
#define A_BYTES (128u * LDA * 2u)                       // 133120
__device__ __align__(1024) unsigned char g_hA[2][2][A_BYTES];
__device__ unsigned int g_ctr[2];                       // per-direction step barrier

// ---------------- JAX threefry2x32 (bit-exact, 20 rounds) ----------------
__device__ __forceinline__ uint32_t rotl32(uint32_t x, int r) { return (x << r) | (x >> (32 - r)); }

__device__ __forceinline__ void tf2x32(uint32_t k0, uint32_t k1, uint32_t& x0, uint32_t& x1) {
    uint32_t k2 = k0 ^ k1 ^ 0x1BD11BDAu;
    x0 += k0; x1 += k1;
#define TFR(r) { x0 += x1; x1 = rotl32(x1, r); x1 ^= x0; }
    TFR(13) TFR(15) TFR(26) TFR(6)   x0 += k1; x1 += k2 + 1u;
    TFR(17) TFR(29) TFR(16) TFR(24)  x0 += k2; x1 += k0 + 2u;
    TFR(13) TFR(15) TFR(26) TFR(6)   x0 += k0; x1 += k1 + 3u;
    TFR(17) TFR(29) TFR(16) TFR(24)  x0 += k1; x1 += k2 + 4u;
    TFR(13) TFR(15) TFR(26) TFR(6)   x0 += k2; x1 += k0 + 5u;
#undef TFR
}

__device__ __forceinline__ uint32_t pbits(uint32_t k0, uint32_t k1, uint32_t i) {
    uint32_t x0 = 0u, x1 = i;
    tf2x32(k0, k1, x0, x1);
    return x0 ^ x1;
}

__device__ __forceinline__ float u01(uint32_t bits) {
    return __uint_as_float((bits >> 9) | 0x3f800000u) - 1.0f;
}
__device__ __forceinline__ float sigm(float x) { return 1.0f / (1.0f + expf(-x)); }

// ---------------- K1: key derivation ----------------
__global__ void rng_setup_kernel() {
    int tid = threadIdx.x;
    __shared__ uint32_t s[4];
    if (tid == 0) {
        g_ctr[0] = 0u; g_ctr[1] = 0u;
        uint32_t a, b;
        a = 0u; b = 0u; tf2x32(0u, 42u, a, b); g_kd = make_uint2(a, b);
        a = 0u; b = 1u; tf2x32(0u, 42u, a, b); s[0] = a; s[1] = b;   // kf
        a = 0u; b = 2u; tf2x32(0u, 42u, a, b); s[2] = a; s[3] = b;   // kb
    }
    __syncthreads();
    if (tid < 2) {
        uint32_t k0 = s[tid * 2], k1 = s[tid * 2 + 1];
        for (int t = 0; t < 1024; ++t) {
            uint32_t z0 = 0u, z1 = 0u; tf2x32(k0, k1, z0, z1);
            uint32_t n0 = 0u, n1 = 1u; tf2x32(k0, k1, n0, n1);
            g_kz[tid * 1024 + t] = make_uint2(z0, z1);
            k0 = n0; k1 = n1;
        }
    }
}

// ---------------- K2: vocab base table ----------------
__global__ void __launch_bounds__(256) base_kernel(const float* __restrict__ embed,
                                                   const float* __restrict__ Wf,
                                                   const float* __restrict__ Wb) {
    int dir = blockIdx.z;
    const float* W = dir ? Wb : Wf;
    int g = blockIdx.x * 256 + threadIdx.x;
    int v0 = blockIdx.y * 4;
    float acc0 = 0.f, acc1 = 0.f, acc2 = 0.f, acc3 = 0.f;
#pragma unroll 4
    for (int d = 0; d < 512; ++d) {
        float w = W[(size_t)d * 2048 + g];
        acc0 = fmaf(embed[(size_t)(v0 + 0) * 512 + d], w, acc0);
        acc1 = fmaf(embed[(size_t)(v0 + 1) * 512 + d], w, acc1);
        acc2 = fmaf(embed[(size_t)(v0 + 2) * 512 + d], w, acc2);
        acc3 = fmaf(embed[(size_t)(v0 + 3) * 512 + d], w, acc3);
    }
    g_base[dir][v0 + 0][g] = acc0;
    g_base[dir][v0 + 1][g] = acc1;
    g_base[dir][v0 + 2][g] = acc2;
    g_base[dir][v0 + 3][g] = acc3;
}

// ---------------- K3: dropout lists ----------------
__global__ void __launch_bounds__(256) drop_kernel(const int* __restrict__ tokens,
                                                   const float* __restrict__ embed) {
    unsigned row = (blockIdx.x * 256u + threadIdx.x) >> 5;
    int lane = threadIdx.x & 31;
    uint2 kd = g_kd;
    int tok = tokens[row];
    const float* erow = &embed[(size_t)tok * 512];
    uint2* outp = &g_dropPack[(size_t)row * 128];
    unsigned count = 0;
#pragma unroll 4
    for (int it = 0; it < 16; ++it) {
        int d = it * 32 + lane;
        uint32_t bits = pbits(kd.x, kd.y, row * 512u + (unsigned)d);
        bool dropped = !(u01(bits) < 0.9f);
        unsigned m = __ballot_sync(0xffffffffu, dropped);
        if (dropped) {
            unsigned pos = count + __popc(m & ((1u << lane) - 1u));
            outp[pos] = make_uint2((unsigned)d, __float_as_uint(erow[d]));
        }
        count += __popc(m);
    }
    if (lane == 0) g_dropN[row] = count;
}

// ---------------- K4: zoneout masks ----------------
__global__ void zoneout_kernel() {
    size_t gi = (size_t)blockIdx.x * 256 + threadIdx.x;
    unsigned pair = (unsigned)(gi & 32767u);
    unsigned st = (unsigned)(gi >> 15);
    uint2 k = g_kz[st];
    uint32_t bh = pbits(k.x, k.y, pair);
    uint32_t bc = pbits(k.x, k.y, pair + 32768u);
    g_zb[gi] = (unsigned char)(((u01(bh) < 0.1f) ? 1u : 0u) | ((u01(bc) < 0.1f) ? 2u : 0u));
}

// ---------------- K5: projection (base + sparse dropout correction) ----------------
#define CORR_SMEM (512 * 64 * 4)

__global__ void __launch_bounds__(256, 1) proj_corr_kernel(const int* __restrict__ tokens,
                                                           const float* __restrict__ Wf,
                                                           const float* __restrict__ Wb,
                                                           const float* __restrict__ bf,
                                                           const float* __restrict__ bb) {
    extern __shared__ float sW[];
    int dir = blockIdx.x >> 5;
    int slice = blockIdx.x & 31;
    int g0 = slice * 64;
    const float* W = dir ? Wb : Wf;
    const float* bias = dir ? bb : bf;
    float* pre = dir ? g_preB : g_preF;
    const float* base = &g_base[dir][0][0];
    int tid = threadIdx.x;

    for (int i = tid; i < 512 * 64; i += 256)
        sW[i] = W[(size_t)(i >> 6) * 2048 + g0 + (i & 63)];
    __syncthreads();

    int lane = tid & 31, w = tid >> 5;
    float2 bv = *(const float2*)&bias[g0 + lane * 2];
    int rEnd = blockIdx.y * 2048 + 2048;
    for (int r = blockIdx.y * 2048 + w; r < rEnd; r += 8) {
        int tok = tokens[r];
        unsigned n = g_dropN[r];
        const uint2* lst = &g_dropPack[(size_t)r * 128];
        float2 acc = *(const float2*)&base[(size_t)tok * 2048 + g0 + lane * 2];
        for (unsigned j0 = 0; j0 < n; j0 += 32) {
            uint2 e = make_uint2(0u, 0u);
            if (j0 + lane < n) e = __ldcg(&lst[j0 + lane]);
            unsigned m = n - j0; if (m > 32u) m = 32u;
            for (unsigned jj = 0; jj < m; ++jj) {
                unsigned dx = __shfl_sync(0xffffffffu, e.x, jj);
                unsigned dv = __shfl_sync(0xffffffffu, e.y, jj);
                float val = __uint_as_float(dv);
                float2 wv = *(const float2*)&sW[dx * 64 + lane * 2];
                acc.x = fmaf(-val, wv.x, acc.x);
                acc.y = fmaf(-val, wv.y, acc.y);
            }
        }
        int b = r >> 10, t = r & 1023;
        float2 o;
        o.x = fmaf(acc.x, (1.0f / 0.9f), bv.x);
        o.y = fmaf(acc.y, (1.0f / 0.9f), bv.y);
        *(float2*)&pre[(((size_t)t * 64) + b) * 2048 + g0 + lane * 2] = o;
    }
}

// ---------------- K6: persistent bidirectional LSTM scan — WMMA (HMMA) matvec ----------------
// Per CTA (128): dir, 8 hidden dims. A = [h_hi; h_lo] (128x512 bf16 row-major, ld=520),
// B = W_hi / W_lo (32 cols x 512 k, col-major, ld=520). D (128x32 fp32, ld=40):
// preact[b][col] = D[b][col] + D[b+64][col]. Warp w = m-tile w (of 8), both n-tiles.
#define SA_OFF   0
#define SBHI_OFF (128 * LDA * 2)                    // 133120
#define SBLO_OFF (SBHI_OFF + 32 * LDA * 2)          // 166400
#define SD_OFF   (SBLO_OFF + 32 * LDA * 2)          // 199680
#define LDD 40
#define SCAN_SMEM (SD_OFF + 128 * LDD * 4)          // 220160

__device__ __forceinline__ void wait_par(uint32_t bar, unsigned p) {
    asm volatile(
        "{\n\t.reg .pred P;\n\t"
        "WL_%=:\n\t"
        "mbarrier.try_wait.parity.acquire.cta.shared::cta.b64 P, [%0], %1, 0x989680;\n\t"
        "@P bra WD_%=;\n\t"
        "bra WL_%=;\n\t"
        "WD_%=:\n\t}"
        :: "r"(bar), "r"(p) : "memory");
}

__global__ void __launch_bounds__(256, 1) scan_kernel(const int* __restrict__ lengths,
                                                      const float* __restrict__ Wf,
                                                      const float* __restrict__ Wb,
                                                      float* __restrict__ out) {
    extern __shared__ unsigned char smem[];
    __nv_bfloat16* sA   = (__nv_bfloat16*)(smem + SA_OFF);
    __nv_bfloat16* sBhi = (__nv_bfloat16*)(smem + SBHI_OFF);
    __nv_bfloat16* sBlo = (__nv_bfloat16*)(smem + SBLO_OFF);
    float* sD = (float*)(smem + SD_OFF);
    __shared__ int sLen[64];
    __shared__ __align__(8) unsigned long long tma_bar;

    int dir = blockIdx.x >> 6, cta = blockIdx.x & 63, d0 = cta * 8;
    int tid = threadIdx.x, wid = tid >> 5;
    const float* W = dir ? Wb : Wf;

    uint32_t sA_addr   = (uint32_t)__cvta_generic_to_shared(sA);
    uint32_t tbar_addr = (uint32_t)__cvta_generic_to_shared(&tma_bar);
    if (tid == 0)
        asm volatile("mbarrier.init.shared.b64 [%0], 1;" :: "r"(tbar_addr) : "memory");

    // W slice -> bf16 hi/lo, col-major (k contiguous), one-time
    for (int i = tid; i < 32 * 512; i += 256) {
        int n = i & 31, k = i >> 5;
        float w = W[(size_t)(512 + k) * 2048 + ((n >> 3) << 9) + d0 + (n & 7)];
        __nv_bfloat16 hi = __float2bfloat16(w);
        __nv_bfloat16 lo = __float2bfloat16(w - __bfloat162float(hi));
        sBhi[n * LDA + k] = hi;
        sBlo[n * LDA + k] = lo;
    }
    if (tid < 64) sLen[tid] = lengths[tid];
    __syncthreads();

    int q = tid >> 6, b = tid & 63;
    int dd = q * 2, d = d0 + dd;
    float c0r = 0.f, c1r = 0.f;
    volatile unsigned int* ctr = &g_ctr[dir];
    const float* pre = dir ? g_preB : g_preF;
    const unsigned char* zbase = &g_zb[(size_t)dir * 1024 * 32768];

    for (int s = 0; s < 1024; ++s) {
        int tx = dir ? (1023 - s) : s;

        // ---- stage A tile via one bulk copy ----
        if (tid == 0) {
            const unsigned char* src = g_hA[dir][s & 1];
            asm volatile("mbarrier.arrive.expect_tx.shared.b64 _, [%0], %1;"
                         :: "r"(tbar_addr), "r"(A_BYTES) : "memory");
            asm volatile("cp.async.bulk.shared::cta.global.mbarrier::complete_tx::bytes [%0], [%1], %2, [%3];"
                         :: "r"(sA_addr), "l"(src), "r"(A_BYTES), "r"(tbar_addr) : "memory");
        }
        wait_par(tbar_addr, (unsigned)(s & 1));

        // ---- prefetch x-projection, zoneout bits, previous h (hi+lo from A tile) ----
        size_t prow = ((size_t)tx * 64 + b) * 2048 + (size_t)d;
        float2 pxi = *(const float2*)&pre[prow];
        float2 pxg = *(const float2*)&pre[prow + 512];
        float2 pxf = *(const float2*)&pre[prow + 1024];
        float2 pxo = *(const float2*)&pre[prow + 1536];
        const unsigned char* zp = &zbase[((size_t)s << 15) + b * 512 + d];
        unsigned char z0 = zp[0], z1 = zp[1];
        uint32_t hbits = *(const uint32_t*)&sA[b * LDA + d];
        uint32_t lbits = *(const uint32_t*)&sA[(b + 64) * LDA + d];
        float hp0 = __bfloat162float(__ushort_as_bfloat16((unsigned short)(hbits & 0xffffu)))
                  + __bfloat162float(__ushort_as_bfloat16((unsigned short)(lbits & 0xffffu)));
        float hp1 = __bfloat162float(__ushort_as_bfloat16((unsigned short)(hbits >> 16)))
                  + __bfloat162float(__ushort_as_bfloat16((unsigned short)(lbits >> 16)));

        // ---- WMMA: D = A @ (B_hi + B_lo), fp32 accum; warp w = rows [16w,16w+16) ----
        {
            wmma::fragment<wmma::accumulator, 16, 16, 16, float> acc0, acc1;
            wmma::fill_fragment(acc0, 0.0f);
            wmma::fill_fragment(acc1, 0.0f);
            const __nv_bfloat16* arow = sA + wid * 16 * LDA;
#pragma unroll 8
            for (int kt = 0; kt < 32; ++kt) {
                wmma::fragment<wmma::matrix_a, 16, 16, 16, __nv_bfloat16, wmma::row_major> af;
                wmma::load_matrix_sync(af, arow + kt * 16, LDA);
                wmma::fragment<wmma::matrix_b, 16, 16, 16, __nv_bfloat16, wmma::col_major> bf;
                wmma::load_matrix_sync(bf, sBhi + kt * 16, LDA);
                wmma::mma_sync(acc0, af, bf, acc0);
                wmma::load_matrix_sync(bf, sBhi + 16 * LDA + kt * 16, LDA);
                wmma::mma_sync(acc1, af, bf, acc1);
                wmma::load_matrix_sync(bf, sBlo + kt * 16, LDA);
                wmma::mma_sync(acc0, af, bf, acc0);
                wmma::load_matrix_sync(bf, sBlo + 16 * LDA + kt * 16, LDA);
                wmma::mma_sync(acc1, af, bf, acc1);
            }
            wmma::store_matrix_sync(sD + wid * 16 * LDD, acc0, LDD, wmma::mem_row_major);
            wmma::store_matrix_sync(sD + wid * 16 * LDD + 16, acc1, LDD, wmma::mem_row_major);
        }
        __syncthreads();

        // ---- gates + zoneout ----
        if (dir && (1023 - s) < sLen[b] - 1) { c0r = 0.f; c1r = 0.f; }
        const float* dt = &sD[b * LDD];
        const float* db = &sD[(b + 64) * LDD];
        float a_i0 = dt[dd] + db[dd],           a_i1 = dt[dd + 1] + db[dd + 1];
        float a_g0 = dt[8 + dd] + db[8 + dd],   a_g1 = dt[9 + dd] + db[9 + dd];
        float a_f0 = dt[16 + dd] + db[16 + dd], a_f1 = dt[17 + dd] + db[17 + dd];
        float a_o0 = dt[24 + dd] + db[24 + dd], a_o1 = dt[25 + dd] + db[25 + dd];
        float f0 = sigm(pxf.x + a_f0 + 1.f), f1 = sigm(pxf.y + a_f1 + 1.f);
        float o0 = sigm(pxo.x + a_o0), o1 = sigm(pxo.y + a_o1);
        float cn0 = f0 * c0r + sigm(pxi.x + a_i0) * tanhf(pxg.x + a_g0);
        float cn1 = f1 * c1r + sigm(pxi.y + a_i1) * tanhf(pxg.y + a_g1);
        float hn0 = o0 * tanhf(cn0);
        float hn1 = o1 * tanhf(cn1);
        float ho0 = (z0 & 1) ? hp0 : hn0;
        float ho1 = (z1 & 1) ? hp1 : hn1;
        c0r = (z0 & 2) ? c0r : cn0;
        c1r = (z1 & 2) ? c1r : cn1;

        // ---- output + next-step h (bwd reset pre-applied), stored as bf16 hi/lo ----
        *(float2*)&out[(((size_t)b << 10) + tx) * 1024 + ((size_t)dir << 9) + d] = make_float2(ho0, ho1);

        float w0 = ho0, w1 = ho1;
        if (dir && (1022 - s) < sLen[b] - 1) { w0 = 0.f; w1 = 0.f; }
        __nv_bfloat16 h0 = __float2bfloat16(w0), h1 = __float2bfloat16(w1);
        __nv_bfloat16 l0 = __float2bfloat16(w0 - __bfloat162float(h0));
        __nv_bfloat16 l1 = __float2bfloat16(w1 - __bfloat162float(h1));
        unsigned char* hw = g_hA[dir][(s + 1) & 1];
        uint32_t hv = (uint32_t)__bfloat16_as_ushort(h0) | ((uint32_t)__bfloat16_as_ushort(h1) << 16);
        uint32_t lv = (uint32_t)__bfloat16_as_ushort(l0) | ((uint32_t)__bfloat16_as_ushort(l1) << 16);
        __stcg((uint32_t*)(hw + (size_t)(b * LDA + d) * 2), hv);
        __stcg((uint32_t*)(hw + (size_t)((b + 64) * LDA + d) * 2), lv);

        // ---- per-direction grid barrier ----
        __syncthreads();
        if (s < 1023) {
            if (tid == 0) {
                __threadfence();
                atomicAdd((unsigned int*)ctr, 1u);
                unsigned int target = 64u * (unsigned)(s + 1);
                while (*ctr < target) __nanosleep(64);
                __threadfence();
            }
            __syncthreads();
        }
    }
}

// ---------------- launch ----------------
extern "C" void kernel_launch(void* const* d_in, const int* in_sizes, int n_in,
                              void* d_out, int out_size) {
    (void)in_sizes; (void)n_in; (void)out_size;
    const int*   tokens  = (const int*)d_in[0];
    const int*   lengths = (const int*)d_in[1];
    const float* embed   = (const float*)d_in[2];
    const float* Wf      = (const float*)d_in[3];
    const float* bf      = (const float*)d_in[4];
    const float* Wb      = (const float*)d_in[5];
    const float* bb      = (const float*)d_in[6];
    float* out = (float*)d_out;

    cudaFuncSetAttribute(scan_kernel, cudaFuncAttributeMaxDynamicSharedMemorySize, SCAN_SMEM);
    cudaFuncSetAttribute(proj_corr_kernel, cudaFuncAttributeMaxDynamicSharedMemorySize, CORR_SMEM);

    void* hA_ptr = nullptr;
    cudaGetSymbolAddress(&hA_ptr, g_hA);

    rng_setup_kernel<<<1, 64>>>();
    base_kernel<<<dim3(8, 64, 2), 256>>>(embed, Wf, Wb);
    drop_kernel<<<8192, 256>>>(tokens, embed);
    zoneout_kernel<<<(2u * 1024u * 32768u) / 256u, 256>>>();
    cudaMemsetAsync(hA_ptr, 0, (size_t)2 * 2 * A_BYTES);
    proj_corr_kernel<<<dim3(64, 32), 256, CORR_SMEM>>>(tokens, Wf, Wb, bf, bb);
    scan_kernel<<<128, 256, SCAN_SMEM>>>(lengths, Wf, Wb, out);
}

// round 11
// speedup vs baseline: 2.9065x; 1.0435x over previous
#include <cuda_runtime.h>
#include <cuda_bf16.h>
#include <mma.h>
#include <cstdint>
#include <cstddef>

using namespace nvcuda;

// ---------------- device scratch (static, no runtime alloc) ----------------
__device__ float g_preF[(size_t)1024 * 64 * 2048];      // x@Wf[:512]+bf, time-major [t][b][g]
__device__ float g_preB[(size_t)1024 * 64 * 2048];      // x@Wb[:512]+bb
__device__ float g_base[2][256][2048];                  // embed@W[:512] per vocab entry
__device__ uint2 g_dropPack[(size_t)65536 * 128];       // per row: (d, bits(e[tok][d])) dropped entries
__device__ unsigned int g_dropN[65536];                 // per row: dropped count
__device__ unsigned char g_zb[(size_t)2 * 1024 * 32768];// zoneout bits: bit0=keep h, bit1=keep c
__device__ uint2 g_kz[2 * 1024];                        // per-step zoneout keys (fwd, bwd)
__device__ uint2 g_kd;                                  // dropout key
// h exchange: A-tile byte image, rows 0-63 = h_hi (bf16), rows 64-127 = h_lo, ld=520 bf16
#define LDA 520
#define A_BYTES (128u * LDA * 2u)                       // 133120
__device__ __align__(1024) unsigned char g_hA[2][2][A_BYTES];
// per-CTA step flags, padded to 128B (one L2 line each) — no atomic serialization
struct FlagLine { unsigned v; unsigned pad[31]; };
__device__ FlagLine g_flag[2][64];

// ---------------- JAX threefry2x32 (bit-exact, 20 rounds) ----------------
__device__ __forceinline__ uint32_t rotl32(uint32_t x, int r) { return (x << r) | (x >> (32 - r)); }

__device__ __forceinline__ void tf2x32(uint32_t k0, uint32_t k1, uint32_t& x0, uint32_t& x1) {
    uint32_t k2 = k0 ^ k1 ^ 0x1BD11BDAu;
    x0 += k0; x1 += k1;
#define TFR(r) { x0 += x1; x1 = rotl32(x1, r); x1 ^= x0; }
    TFR(13) TFR(15) TFR(26) TFR(6)   x0 += k1; x1 += k2 + 1u;
    TFR(17) TFR(29) TFR(16) TFR(24)  x0 += k2; x1 += k0 + 2u;
    TFR(13) TFR(15) TFR(26) TFR(6)   x0 += k0; x1 += k1 + 3u;
    TFR(17) TFR(29) TFR(16) TFR(24)  x0 += k1; x1 += k2 + 4u;
    TFR(13) TFR(15) TFR(26) TFR(6)   x0 += k2; x1 += k0 + 5u;
#undef TFR
}

__device__ __forceinline__ uint32_t pbits(uint32_t k0, uint32_t k1, uint32_t i) {
    uint32_t x0 = 0u, x1 = i;
    tf2x32(k0, k1, x0, x1);
    return x0 ^ x1;
}

__device__ __forceinline__ float u01(uint32_t bits) {
    return __uint_as_float((bits >> 9) | 0x3f800000u) - 1.0f;
}
__device__ __forceinline__ float sigm(float x) { return 1.0f / (1.0f + expf(-x)); }

// ---------------- K1: key derivation + flag reset ----------------
__global__ void rng_setup_kernel() {
    int tid = threadIdx.x;
    __shared__ uint32_t s[4];
    if (tid < 128) g_flag[tid >> 6][tid & 63].v = 0u;
    if (tid == 0) {
        uint32_t a, b;
        a = 0u; b = 0u; tf2x32(0u, 42u, a, b); g_kd = make_uint2(a, b);
        a = 0u; b = 1u; tf2x32(0u, 42u, a, b); s[0] = a; s[1] = b;   // kf
        a = 0u; b = 2u; tf2x32(0u, 42u, a, b); s[2] = a; s[3] = b;   // kb
    }
    __syncthreads();
    if (tid < 2) {
        uint32_t k0 = s[tid * 2], k1 = s[tid * 2 + 1];
        for (int t = 0; t < 1024; ++t) {
            uint32_t z0 = 0u, z1 = 0u; tf2x32(k0, k1, z0, z1);
            uint32_t n0 = 0u, n1 = 1u; tf2x32(k0, k1, n0, n1);
            g_kz[tid * 1024 + t] = make_uint2(z0, z1);
            k0 = n0; k1 = n1;
        }
    }
}

// ---------------- K2: vocab base table ----------------
__global__ void __launch_bounds__(256) base_kernel(const float* __restrict__ embed,
                                                   const float* __restrict__ Wf,
                                                   const float* __restrict__ Wb) {
    int dir = blockIdx.z;
    const float* W = dir ? Wb : Wf;
    int g = blockIdx.x * 256 + threadIdx.x;
    int v0 = blockIdx.y * 4;
    float acc0 = 0.f, acc1 = 0.f, acc2 = 0.f, acc3 = 0.f;
#pragma unroll 4
    for (int d = 0; d < 512; ++d) {
        float w = W[(size_t)d * 2048 + g];
        acc0 = fmaf(embed[(size_t)(v0 + 0) * 512 + d], w, acc0);
        acc1 = fmaf(embed[(size_t)(v0 + 1) * 512 + d], w, acc1);
        acc2 = fmaf(embed[(size_t)(v0 + 2) * 512 + d], w, acc2);
        acc3 = fmaf(embed[(size_t)(v0 + 3) * 512 + d], w, acc3);
    }
    g_base[dir][v0 + 0][g] = acc0;
    g_base[dir][v0 + 1][g] = acc1;
    g_base[dir][v0 + 2][g] = acc2;
    g_base[dir][v0 + 3][g] = acc3;
}

// ---------------- K3: dropout lists ----------------
__global__ void __launch_bounds__(256) drop_kernel(const int* __restrict__ tokens,
                                                   const float* __restrict__ embed) {
    unsigned row = (blockIdx.x * 256u + threadIdx.x) >> 5;
    int lane = threadIdx.x & 31;
    uint2 kd = g_kd;
    int tok = tokens[row];
    const float* erow = &embed[(size_t)tok * 512];
    uint2* outp = &g_dropPack[(size_t)row * 128];
    unsigned count = 0;
#pragma unroll 4
    for (int it = 0; it < 16; ++it) {
        int d = it * 32 + lane;
        uint32_t bits = pbits(kd.x, kd.y, row * 512u + (unsigned)d);
        bool dropped = !(u01(bits) < 0.9f);
        unsigned m = __ballot_sync(0xffffffffu, dropped);
        if (dropped) {
            unsigned pos = count + __popc(m & ((1u << lane) - 1u));
            outp[pos] = make_uint2((unsigned)d, __float_as_uint(erow[d]));
        }
        count += __popc(m);
    }
    if (lane == 0) g_dropN[row] = count;
}

// ---------------- K4: zoneout masks ----------------
__global__ void zoneout_kernel() {
    size_t gi = (size_t)blockIdx.x * 256 + threadIdx.x;
    unsigned pair = (unsigned)(gi & 32767u);
    unsigned st = (unsigned)(gi >> 15);
    uint2 k = g_kz[st];
    uint32_t bh = pbits(k.x, k.y, pair);
    uint32_t bc = pbits(k.x, k.y, pair + 32768u);
    g_zb[gi] = (unsigned char)(((u01(bh) < 0.1f) ? 1u : 0u) | ((u01(bc) < 0.1f) ? 2u : 0u));
}

// ---------------- K5: projection (base + sparse dropout correction) ----------------
#define CORR_SMEM (512 * 64 * 4)

__global__ void __launch_bounds__(256, 1) proj_corr_kernel(const int* __restrict__ tokens,
                                                           const float* __restrict__ Wf,
                                                           const float* __restrict__ Wb,
                                                           const float* __restrict__ bf,
                                                           const float* __restrict__ bb) {
    extern __shared__ float sW[];
    int dir = blockIdx.x >> 5;
    int slice = blockIdx.x & 31;
    int g0 = slice * 64;
    const float* W = dir ? Wb : Wf;
    const float* bias = dir ? bb : bf;
    float* pre = dir ? g_preB : g_preF;
    const float* base = &g_base[dir][0][0];
    int tid = threadIdx.x;

    for (int i = tid; i < 512 * 64; i += 256)
        sW[i] = W[(size_t)(i >> 6) * 2048 + g0 + (i & 63)];
    __syncthreads();

    int lane = tid & 31, w = tid >> 5;
    float2 bv = *(const float2*)&bias[g0 + lane * 2];
    int rEnd = blockIdx.y * 4096 + 4096;
    for (int r = blockIdx.y * 4096 + w; r < rEnd; r += 8) {
        int tok = tokens[r];
        unsigned n = g_dropN[r];
        const uint2* lst = &g_dropPack[(size_t)r * 128];
        float2 acc = *(const float2*)&base[(size_t)tok * 2048 + g0 + lane * 2];
        for (unsigned j0 = 0; j0 < n; j0 += 32) {
            uint2 e = make_uint2(0u, 0u);
            if (j0 + lane < n) e = __ldcg(&lst[j0 + lane]);   // lanes past n: val=0 -> harmless FMA
#pragma unroll
            for (int jj = 0; jj < 32; ++jj) {
                unsigned dx = __shfl_sync(0xffffffffu, e.x, jj);
                unsigned dv = __shfl_sync(0xffffffffu, e.y, jj);
                float val = __uint_as_float(dv);
                float2 wv = *(const float2*)&sW[dx * 64 + lane * 2];
                acc.x = fmaf(-val, wv.x, acc.x);
                acc.y = fmaf(-val, wv.y, acc.y);
            }
        }
        int b = r >> 10, t = r & 1023;
        float2 o;
        o.x = fmaf(acc.x, (1.0f / 0.9f), bv.x);
        o.y = fmaf(acc.y, (1.0f / 0.9f), bv.y);
        *(float2*)&pre[(((size_t)t * 64) + b) * 2048 + g0 + lane * 2] = o;
    }
}

// ---------------- K6: persistent bidirectional LSTM scan — WMMA (HMMA) matvec ----------------
#define SA_OFF   0
#define SBHI_OFF (128 * LDA * 2)                    // 133120
#define SBLO_OFF (SBHI_OFF + 32 * LDA * 2)          // 166400
#define SD_OFF   (SBLO_OFF + 32 * LDA * 2)          // 199680
#define LDD 40
#define SCAN_SMEM (SD_OFF + 128 * LDD * 4)          // 220160

__device__ __forceinline__ void wait_par(uint32_t bar, unsigned p) {
    asm volatile(
        "{\n\t.reg .pred P;\n\t"
        "WL_%=:\n\t"
        "mbarrier.try_wait.parity.acquire.cta.shared::cta.b64 P, [%0], %1, 0x989680;\n\t"
        "@P bra WD_%=;\n\t"
        "bra WL_%=;\n\t"
        "WD_%=:\n\t}"
        :: "r"(bar), "r"(p) : "memory");
}

__global__ void __launch_bounds__(256, 1) scan_kernel(const int* __restrict__ lengths,
                                                      const float* __restrict__ Wf,
                                                      const float* __restrict__ Wb,
                                                      float* __restrict__ out) {
    extern __shared__ unsigned char smem[];
    __nv_bfloat16* sA   = (__nv_bfloat16*)(smem + SA_OFF);
    __nv_bfloat16* sBhi = (__nv_bfloat16*)(smem + SBHI_OFF);
    __nv_bfloat16* sBlo = (__nv_bfloat16*)(smem + SBLO_OFF);
    float* sD = (float*)(smem + SD_OFF);
    __shared__ int sLen[64];
    __shared__ __align__(8) unsigned long long tma_bar;

    int dir = blockIdx.x >> 6, cta = blockIdx.x & 63, d0 = cta * 8;
    int tid = threadIdx.x, wid = tid >> 5;
    const float* W = dir ? Wb : Wf;

    uint32_t sA_addr   = (uint32_t)__cvta_generic_to_shared(sA);
    uint32_t tbar_addr = (uint32_t)__cvta_generic_to_shared(&tma_bar);
    if (tid == 0)
        asm volatile("mbarrier.init.shared.b64 [%0], 1;" :: "r"(tbar_addr) : "memory");

    // W slice -> bf16 hi/lo, col-major (k contiguous), one-time
    for (int i = tid; i < 32 * 512; i += 256) {
        int n = i & 31, k = i >> 5;
        float w = W[(size_t)(512 + k) * 2048 + ((n >> 3) << 9) + d0 + (n & 7)];
        __nv_bfloat16 hi = __float2bfloat16(w);
        __nv_bfloat16 lo = __float2bfloat16(w - __bfloat162float(hi));
        sBhi[n * LDA + k] = hi;
        sBlo[n * LDA + k] = lo;
    }
    if (tid < 64) sLen[tid] = lengths[tid];
    __syncthreads();

    int q = tid >> 6, b = tid & 63;
    int dd = q * 2, d = d0 + dd;
    float c0r = 0.f, c1r = 0.f;
    const float* pre = dir ? g_preB : g_preF;
    const unsigned char* zbase = &g_zb[(size_t)dir * 1024 * 32768];
    int mg = wid >> 1, nt = wid & 1;                 // warp tile: 2 m-tiles x 1 n-tile

    for (int s = 0; s < 1024; ++s) {
        int tx = dir ? (1023 - s) : s;

        // ---- stage A tile via one bulk copy ----
        if (tid == 0) {
            const unsigned char* src = g_hA[dir][s & 1];
            asm volatile("mbarrier.arrive.expect_tx.shared.b64 _, [%0], %1;"
                         :: "r"(tbar_addr), "r"(A_BYTES) : "memory");
            asm volatile("cp.async.bulk.shared::cta.global.mbarrier::complete_tx::bytes [%0], [%1], %2, [%3];"
                         :: "r"(sA_addr), "l"(src), "r"(A_BYTES), "r"(tbar_addr) : "memory");
        }
        wait_par(tbar_addr, (unsigned)(s & 1));

        // ---- prefetch x-projection, zoneout bits, previous h ----
        size_t prow = ((size_t)tx * 64 + b) * 2048 + (size_t)d;
        float2 pxi = *(const float2*)&pre[prow];
        float2 pxg = *(const float2*)&pre[prow + 512];
        float2 pxf = *(const float2*)&pre[prow + 1024];
        float2 pxo = *(const float2*)&pre[prow + 1536];
        const unsigned char* zp = &zbase[((size_t)s << 15) + b * 512 + d];
        unsigned char z0 = zp[0], z1 = zp[1];
        uint32_t hbits = *(const uint32_t*)&sA[b * LDA + d];
        uint32_t lbits = *(const uint32_t*)&sA[(b + 64) * LDA + d];
        float hp0 = __bfloat162float(__ushort_as_bfloat16((unsigned short)(hbits & 0xffffu)))
                  + __bfloat162float(__ushort_as_bfloat16((unsigned short)(lbits & 0xffffu)));
        float hp1 = __bfloat162float(__ushort_as_bfloat16((unsigned short)(hbits >> 16)))
                  + __bfloat162float(__ushort_as_bfloat16((unsigned short)(lbits >> 16)));

        // ---- WMMA: warp = m-tiles {2mg, 2mg+1} x n-tile nt; A,B frags each reused 2x ----
        {
            wmma::fragment<wmma::accumulator, 16, 16, 16, float> acc0, acc1;
            wmma::fill_fragment(acc0, 0.0f);
            wmma::fill_fragment(acc1, 0.0f);
            const __nv_bfloat16* a0p = sA + (mg * 2) * 16 * LDA;
            const __nv_bfloat16* a1p = sA + (mg * 2 + 1) * 16 * LDA;
            const __nv_bfloat16* bhp = sBhi + nt * 16 * LDA;
            const __nv_bfloat16* blp = sBlo + nt * 16 * LDA;
#pragma unroll 8
            for (int kt = 0; kt < 32; ++kt) {
                wmma::fragment<wmma::matrix_a, 16, 16, 16, __nv_bfloat16, wmma::row_major> a0f, a1f;
                wmma::fragment<wmma::matrix_b, 16, 16, 16, __nv_bfloat16, wmma::col_major> bhf, blf;
                wmma::load_matrix_sync(a0f, a0p + kt * 16, LDA);
                wmma::load_matrix_sync(a1f, a1p + kt * 16, LDA);
                wmma::load_matrix_sync(bhf, bhp + kt * 16, LDA);
                wmma::load_matrix_sync(blf, blp + kt * 16, LDA);
                wmma::mma_sync(acc0, a0f, bhf, acc0);
                wmma::mma_sync(acc1, a1f, bhf, acc1);
                wmma::mma_sync(acc0, a0f, blf, acc0);
                wmma::mma_sync(acc1, a1f, blf, acc1);
            }
            wmma::store_matrix_sync(sD + (mg * 2) * 16 * LDD + nt * 16, acc0, LDD, wmma::mem_row_major);
            wmma::store_matrix_sync(sD + (mg * 2 + 1) * 16 * LDD + nt * 16, acc1, LDD, wmma::mem_row_major);
        }
        __syncthreads();

        // ---- gates + zoneout ----
        if (dir && (1023 - s) < sLen[b] - 1) { c0r = 0.f; c1r = 0.f; }
        const float* dt = &sD[b * LDD];
        const float* db = &sD[(b + 64) * LDD];
        float a_i0 = dt[dd] + db[dd],           a_i1 = dt[dd + 1] + db[dd + 1];
        float a_g0 = dt[8 + dd] + db[8 + dd],   a_g1 = dt[9 + dd] + db[9 + dd];
        float a_f0 = dt[16 + dd] + db[16 + dd], a_f1 = dt[17 + dd] + db[17 + dd];
        float a_o0 = dt[24 + dd] + db[24 + dd], a_o1 = dt[25 + dd] + db[25 + dd];
        float f0 = sigm(pxf.x + a_f0 + 1.f), f1 = sigm(pxf.y + a_f1 + 1.f);
        float o0 = sigm(pxo.x + a_o0), o1 = sigm(pxo.y + a_o1);
        float cn0 = f0 * c0r + sigm(pxi.x + a_i0) * tanhf(pxg.x + a_g0);
        float cn1 = f1 * c1r + sigm(pxi.y + a_i1) * tanhf(pxg.y + a_g1);
        float hn0 = o0 * tanhf(cn0);
        float hn1 = o1 * tanhf(cn1);
        float ho0 = (z0 & 1) ? hp0 : hn0;
        float ho1 = (z1 & 1) ? hp1 : hn1;
        c0r = (z0 & 2) ? c0r : cn0;
        c1r = (z1 & 2) ? c1r : cn1;

        // ---- next-step h (bwd reset pre-applied), stored as bf16 hi/lo ----
        float w0 = ho0, w1 = ho1;
        if (dir && (1022 - s) < sLen[b] - 1) { w0 = 0.f; w1 = 0.f; }
        __nv_bfloat16 h0 = __float2bfloat16(w0), h1 = __float2bfloat16(w1);
        __nv_bfloat16 l0 = __float2bfloat16(w0 - __bfloat162float(h0));
        __nv_bfloat16 l1 = __float2bfloat16(w1 - __bfloat162float(h1));
        unsigned char* hw = g_hA[dir][(s + 1) & 1];
        uint32_t hv = (uint32_t)__bfloat16_as_ushort(h0) | ((uint32_t)__bfloat16_as_ushort(h1) << 16);
        uint32_t lv = (uint32_t)__bfloat16_as_ushort(l0) | ((uint32_t)__bfloat16_as_ushort(l1) << 16);
        __stcg((uint32_t*)(hw + (size_t)(b * LDA + d) * 2), hv);
        __stcg((uint32_t*)(hw + (size_t)((b + 64) * LDA + d) * 2), lv);

        // ---- flag-based grid barrier; out store overlapped with poll window ----
        __syncthreads();                               // all h stores issued
        if (s < 1023) {
            if (tid == 0) {
                __threadfence();
                *(volatile unsigned*)&g_flag[dir][cta].v = (unsigned)(s + 1);
            }
            *(float2*)&out[(((size_t)b << 10) + tx) * 1024 + ((size_t)dir << 9) + d] = make_float2(ho0, ho1);
            if (tid < 64) {
                volatile unsigned* f = &g_flag[dir][tid].v;
                while (*f < (unsigned)(s + 1)) __nanosleep(64);
            }
            __syncthreads();
        } else {
            *(float2*)&out[(((size_t)b << 10) + tx) * 1024 + ((size_t)dir << 9) + d] = make_float2(ho0, ho1);
        }
    }
}

// ---------------- launch ----------------
extern "C" void kernel_launch(void* const* d_in, const int* in_sizes, int n_in,
                              void* d_out, int out_size) {
    (void)in_sizes; (void)n_in; (void)out_size;
    const int*   tokens  = (const int*)d_in[0];
    const int*   lengths = (const int*)d_in[1];
    const float* embed   = (const float*)d_in[2];
    const float* Wf      = (const float*)d_in[3];
    const float* bf      = (const float*)d_in[4];
    const float* Wb      = (const float*)d_in[5];
    const float* bb      = (const float*)d_in[6];
    float* out = (float*)d_out;

    cudaFuncSetAttribute(scan_kernel, cudaFuncAttributeMaxDynamicSharedMemorySize, SCAN_SMEM);
    cudaFuncSetAttribute(proj_corr_kernel, cudaFuncAttributeMaxDynamicSharedMemorySize, CORR_SMEM);

    void* hA_ptr = nullptr;
    cudaGetSymbolAddress(&hA_ptr, g_hA);

    rng_setup_kernel<<<1, 128>>>();
    base_kernel<<<dim3(8, 64, 2), 256>>>(embed, Wf, Wb);
    drop_kernel<<<8192, 256>>>(tokens, embed);
    zoneout_kernel<<<(2u * 1024u * 32768u) / 256u, 256>>>();
    cudaMemsetAsync(hA_ptr, 0, (size_t)2 * 2 * A_BYTES);
    proj_corr_kernel<<<dim3(64, 16), 256, CORR_SMEM>>>(tokens, Wf, Wb, bf, bb);
    scan_kernel<<<128, 256, SCAN_SMEM>>>(lengths, Wf, Wb, out);
}

// round 12
// speedup vs baseline: 2.9943x; 1.0302x over previous
#include <cuda_runtime.h>
#include <cuda_bf16.h>
#include <mma.h>
#include <cstdint>
#include <cstddef>

using namespace nvcuda;

// ---------------- device scratch (static, no runtime alloc) ----------------
__device__ float g_preF[(size_t)1024 * 64 * 2048];      // x@Wf[:512]+bf, time-major [t][b][g]
__device__ float g_preB[(size_t)1024 * 64 * 2048];      // x@Wb[:512]+bb
__device__ float g_base[2][256][2048];                  // embed@W[:512] per vocab entry
__device__ uint2 g_dropPack[(size_t)65536 * 128];       // per row: (d, bits(e[tok][d])) dropped entries
__device__ unsigned int g_dropN[65536];                 // per row: dropped count
__device__ unsigned char g_zb[(size_t)2 * 1024 * 32768];// zoneout bits: bit0=keep h, bit1=keep c
__device__ uint2 g_kz[2 * 1024];                        // per-step zoneout keys (fwd, bwd)
__device__ uint2 g_kd;                                  // dropout key
// h exchange: A-tile byte image, rows 0-63 = h_hi (bf16), rows 64-127 = h_lo, ld=520 bf16
#define LDA 520
#define A_BYTES (128u * LDA * 2u)                       // 133120
__device__ __align__(1024) unsigned char g_hA[2][2][A_BYTES];
// per-CTA step flags, padded to 128B (one L2 line each) — no atomic serialization
struct FlagLine { unsigned v; unsigned pad[31]; };
__device__ FlagLine g_flag[2][64];

// ---------------- JAX threefry2x32 (bit-exact, 20 rounds) ----------------
__device__ __forceinline__ uint32_t rotl32(uint32_t x, int r) { return (x << r) | (x >> (32 - r)); }

__device__ __forceinline__ void tf2x32(uint32_t k0, uint32_t k1, uint32_t& x0, uint32_t& x1) {
    uint32_t k2 = k0 ^ k1 ^ 0x1BD11BDAu;
    x0 += k0; x1 += k1;
#define TFR(r) { x0 += x1; x1 = rotl32(x1, r); x1 ^= x0; }
    TFR(13) TFR(15) TFR(26) TFR(6)   x0 += k1; x1 += k2 + 1u;
    TFR(17) TFR(29) TFR(16) TFR(24)  x0 += k2; x1 += k0 + 2u;
    TFR(13) TFR(15) TFR(26) TFR(6)   x0 += k0; x1 += k1 + 3u;
    TFR(17) TFR(29) TFR(16) TFR(24)  x0 += k1; x1 += k2 + 4u;
    TFR(13) TFR(15) TFR(26) TFR(6)   x0 += k2; x1 += k0 + 5u;
#undef TFR
}

__device__ __forceinline__ uint32_t pbits(uint32_t k0, uint32_t k1, uint32_t i) {
    uint32_t x0 = 0u, x1 = i;
    tf2x32(k0, k1, x0, x1);
    return x0 ^ x1;
}

__device__ __forceinline__ float u01(uint32_t bits) {
    return __uint_as_float((bits >> 9) | 0x3f800000u) - 1.0f;
}

// ---------------- MUFU-free transcendentals (FMA/ALU pipes only) ----------------
// sigmoid(x) = 1/(1 + e^{-x}); exp2 via magic-round + deg-6 poly; rcp via Newton.
__device__ __forceinline__ float sigm_fast(float x) {
    float t = -x * 1.44269504088896341f;              // -x * log2(e)
    t = fminf(fmaxf(t, -126.0f), 126.0f);
    float z = t + 12582912.0f;                        // RNE round to int (|t| < 2^22)
    int ii = __float_as_int(z) - 0x4B400000;
    float f = t - (z - 12582912.0f);                  // f in [-0.5, 0.5]
    float p =            1.54035303933816e-4f;        // 2^f Taylor deg-6
    p = fmaf(p, f, 1.33335581464284e-3f);
    p = fmaf(p, f, 9.61812910762848e-3f);
    p = fmaf(p, f, 5.55041086648216e-2f);
    p = fmaf(p, f, 2.40226506959101e-1f);
    p = fmaf(p, f, 6.93147180559945e-1f);
    p = fmaf(p, f, 1.0f);
    float e = p * __int_as_float((ii + 127) << 23);   // e^{-x}
    float d = 1.0f + e;
    float y = __int_as_float(0x7EF311C3 - __float_as_int(d));
    y = y * (2.0f - d * y);
    y = y * (2.0f - d * y);
    y = y * (2.0f - d * y);
    return y;
}
__device__ __forceinline__ float tanh_fast(float x) {
    return fmaf(2.0f, sigm_fast(2.0f * x), -1.0f);
}

// ---------------- K1: key derivation + flag reset ----------------
__global__ void rng_setup_kernel() {
    int tid = threadIdx.x;
    __shared__ uint32_t s[4];
    if (tid < 128) g_flag[tid >> 6][tid & 63].v = 0u;
    if (tid == 0) {
        uint32_t a, b;
        a = 0u; b = 0u; tf2x32(0u, 42u, a, b); g_kd = make_uint2(a, b);
        a = 0u; b = 1u; tf2x32(0u, 42u, a, b); s[0] = a; s[1] = b;   // kf
        a = 0u; b = 2u; tf2x32(0u, 42u, a, b); s[2] = a; s[3] = b;   // kb
    }
    __syncthreads();
    if (tid < 2) {
        uint32_t k0 = s[tid * 2], k1 = s[tid * 2 + 1];
        for (int t = 0; t < 1024; ++t) {
            uint32_t z0 = 0u, z1 = 0u; tf2x32(k0, k1, z0, z1);
            uint32_t n0 = 0u, n1 = 1u; tf2x32(k0, k1, n0, n1);
            g_kz[tid * 1024 + t] = make_uint2(z0, z1);
            k0 = n0; k1 = n1;
        }
    }
}

// ---------------- K2: vocab base table ----------------
__global__ void __launch_bounds__(256) base_kernel(const float* __restrict__ embed,
                                                   const float* __restrict__ Wf,
                                                   const float* __restrict__ Wb) {
    int dir = blockIdx.z;
    const float* W = dir ? Wb : Wf;
    int g = blockIdx.x * 256 + threadIdx.x;
    int v0 = blockIdx.y * 4;
    float acc0 = 0.f, acc1 = 0.f, acc2 = 0.f, acc3 = 0.f;
#pragma unroll 4
    for (int d = 0; d < 512; ++d) {
        float w = W[(size_t)d * 2048 + g];
        acc0 = fmaf(embed[(size_t)(v0 + 0) * 512 + d], w, acc0);
        acc1 = fmaf(embed[(size_t)(v0 + 1) * 512 + d], w, acc1);
        acc2 = fmaf(embed[(size_t)(v0 + 2) * 512 + d], w, acc2);
        acc3 = fmaf(embed[(size_t)(v0 + 3) * 512 + d], w, acc3);
    }
    g_base[dir][v0 + 0][g] = acc0;
    g_base[dir][v0 + 1][g] = acc1;
    g_base[dir][v0 + 2][g] = acc2;
    g_base[dir][v0 + 3][g] = acc3;
}

// ---------------- K3: dropout lists ----------------
__global__ void __launch_bounds__(256) drop_kernel(const int* __restrict__ tokens,
                                                   const float* __restrict__ embed) {
    unsigned row = (blockIdx.x * 256u + threadIdx.x) >> 5;
    int lane = threadIdx.x & 31;
    uint2 kd = g_kd;
    int tok = tokens[row];
    const float* erow = &embed[(size_t)tok * 512];
    uint2* outp = &g_dropPack[(size_t)row * 128];
    unsigned count = 0;
#pragma unroll 4
    for (int it = 0; it < 16; ++it) {
        int d = it * 32 + lane;
        uint32_t bits = pbits(kd.x, kd.y, row * 512u + (unsigned)d);
        bool dropped = !(u01(bits) < 0.9f);
        unsigned m = __ballot_sync(0xffffffffu, dropped);
        if (dropped) {
            unsigned pos = count + __popc(m & ((1u << lane) - 1u));
            outp[pos] = make_uint2((unsigned)d, __float_as_uint(erow[d]));
        }
        count += __popc(m);
    }
    if (lane == 0) g_dropN[row] = count;
}

// ---------------- K4: zoneout masks ----------------
__global__ void zoneout_kernel() {
    size_t gi = (size_t)blockIdx.x * 256 + threadIdx.x;
    unsigned pair = (unsigned)(gi & 32767u);
    unsigned st = (unsigned)(gi >> 15);
    uint2 k = g_kz[st];
    uint32_t bh = pbits(k.x, k.y, pair);
    uint32_t bc = pbits(k.x, k.y, pair + 32768u);
    g_zb[gi] = (unsigned char)(((u01(bh) < 0.1f) ? 1u : 0u) | ((u01(bc) < 0.1f) ? 2u : 0u));
}

// ---------------- K5: projection (base + sparse dropout correction) ----------------
#define CORR_SMEM (512 * 64 * 4)

__global__ void __launch_bounds__(256, 1) proj_corr_kernel(const int* __restrict__ tokens,
                                                           const float* __restrict__ Wf,
                                                           const float* __restrict__ Wb,
                                                           const float* __restrict__ bf,
                                                           const float* __restrict__ bb) {
    extern __shared__ float sW[];
    int dir = blockIdx.x >> 5;
    int slice = blockIdx.x & 31;
    int g0 = slice * 64;
    const float* W = dir ? Wb : Wf;
    const float* bias = dir ? bb : bf;
    float* pre = dir ? g_preB : g_preF;
    const float* base = &g_base[dir][0][0];
    int tid = threadIdx.x;

    for (int i = tid; i < 512 * 64; i += 256)
        sW[i] = W[(size_t)(i >> 6) * 2048 + g0 + (i & 63)];
    __syncthreads();

    int lane = tid & 31, w = tid >> 5;
    float2 bv = *(const float2*)&bias[g0 + lane * 2];
    int rEnd = blockIdx.y * 4096 + 4096;
    for (int r = blockIdx.y * 4096 + w; r < rEnd; r += 8) {
        int tok = tokens[r];
        unsigned n = g_dropN[r];
        const uint2* lst = &g_dropPack[(size_t)r * 128];
        float2 acc = *(const float2*)&base[(size_t)tok * 2048 + g0 + lane * 2];
        for (unsigned j0 = 0; j0 < n; j0 += 32) {
            uint2 e = make_uint2(0u, 0u);
            if (j0 + lane < n) e = __ldcg(&lst[j0 + lane]);   // lanes past n: val=0 -> harmless FMA
#pragma unroll
            for (int jj = 0; jj < 32; ++jj) {
                unsigned dx = __shfl_sync(0xffffffffu, e.x, jj);
                unsigned dv = __shfl_sync(0xffffffffu, e.y, jj);
                float val = __uint_as_float(dv);
                float2 wv = *(const float2*)&sW[dx * 64 + lane * 2];
                acc.x = fmaf(-val, wv.x, acc.x);
                acc.y = fmaf(-val, wv.y, acc.y);
            }
        }
        int b = r >> 10, t = r & 1023;
        float2 o;
        o.x = fmaf(acc.x, (1.0f / 0.9f), bv.x);
        o.y = fmaf(acc.y, (1.0f / 0.9f), bv.y);
        *(float2*)&pre[(((size_t)t * 64) + b) * 2048 + g0 + lane * 2] = o;
    }
}

// ---------------- K6: persistent bidirectional LSTM scan — WMMA (HMMA) matvec ----------------
#define SA_OFF   0
#define SBHI_OFF (128 * LDA * 2)                    // 133120
#define SBLO_OFF (SBHI_OFF + 32 * LDA * 2)          // 166400
#define SD_OFF   (SBLO_OFF + 32 * LDA * 2)          // 199680
#define LDD 40
#define SCAN_SMEM (SD_OFF + 128 * LDD * 4)          // 220160

__device__ __forceinline__ void wait_par(uint32_t bar, unsigned p) {
    asm volatile(
        "{\n\t.reg .pred P;\n\t"
        "WL_%=:\n\t"
        "mbarrier.try_wait.parity.acquire.cta.shared::cta.b64 P, [%0], %1, 0x989680;\n\t"
        "@P bra WD_%=;\n\t"
        "bra WL_%=;\n\t"
        "WD_%=:\n\t}"
        :: "r"(bar), "r"(p) : "memory");
}

__global__ void __launch_bounds__(256, 1) scan_kernel(const int* __restrict__ lengths,
                                                      const float* __restrict__ Wf,
                                                      const float* __restrict__ Wb,
                                                      float* __restrict__ out) {
    extern __shared__ unsigned char smem[];
    __nv_bfloat16* sA   = (__nv_bfloat16*)(smem + SA_OFF);
    __nv_bfloat16* sBhi = (__nv_bfloat16*)(smem + SBHI_OFF);
    __nv_bfloat16* sBlo = (__nv_bfloat16*)(smem + SBLO_OFF);
    float* sD = (float*)(smem + SD_OFF);
    __shared__ int sLen[64];
    __shared__ __align__(8) unsigned long long tma_bar;

    int dir = blockIdx.x >> 6, cta = blockIdx.x & 63, d0 = cta * 8;
    int tid = threadIdx.x, wid = tid >> 5;
    const float* W = dir ? Wb : Wf;

    uint32_t sA_addr   = (uint32_t)__cvta_generic_to_shared(sA);
    uint32_t tbar_addr = (uint32_t)__cvta_generic_to_shared(&tma_bar);
    if (tid == 0)
        asm volatile("mbarrier.init.shared.b64 [%0], 1;" :: "r"(tbar_addr) : "memory");

    // W slice -> bf16 hi/lo, col-major (k contiguous), one-time
    for (int i = tid; i < 32 * 512; i += 256) {
        int n = i & 31, k = i >> 5;
        float w = W[(size_t)(512 + k) * 2048 + ((n >> 3) << 9) + d0 + (n & 7)];
        __nv_bfloat16 hi = __float2bfloat16(w);
        __nv_bfloat16 lo = __float2bfloat16(w - __bfloat162float(hi));
        sBhi[n * LDA + k] = hi;
        sBlo[n * LDA + k] = lo;
    }
    if (tid < 64) sLen[tid] = lengths[tid];
    __syncthreads();

    int q = tid >> 6, b = tid & 63;
    int dd = q * 2, d = d0 + dd;
    float c0r = 0.f, c1r = 0.f;
    const float* pre = dir ? g_preB : g_preF;
    const unsigned char* zbase = &g_zb[(size_t)dir * 1024 * 32768];
    int mg = wid >> 1, nt = wid & 1;                 // warp tile: 2 m-tiles x 1 n-tile

    for (int s = 0; s < 1024; ++s) {
        int tx = dir ? (1023 - s) : s;

        // ---- stage A tile via one bulk copy ----
        if (tid == 0) {
            const unsigned char* src = g_hA[dir][s & 1];
            asm volatile("mbarrier.arrive.expect_tx.shared.b64 _, [%0], %1;"
                         :: "r"(tbar_addr), "r"(A_BYTES) : "memory");
            asm volatile("cp.async.bulk.shared::cta.global.mbarrier::complete_tx::bytes [%0], [%1], %2, [%3];"
                         :: "r"(sA_addr), "l"(src), "r"(A_BYTES), "r"(tbar_addr) : "memory");
        }
        wait_par(tbar_addr, (unsigned)(s & 1));

        // ---- prefetch x-projection, zoneout bits, previous h ----
        size_t prow = ((size_t)tx * 64 + b) * 2048 + (size_t)d;
        float2 pxi = *(const float2*)&pre[prow];
        float2 pxg = *(const float2*)&pre[prow + 512];
        float2 pxf = *(const float2*)&pre[prow + 1024];
        float2 pxo = *(const float2*)&pre[prow + 1536];
        const unsigned char* zp = &zbase[((size_t)s << 15) + b * 512 + d];
        unsigned char z0 = zp[0], z1 = zp[1];
        uint32_t hbits = *(const uint32_t*)&sA[b * LDA + d];
        uint32_t lbits = *(const uint32_t*)&sA[(b + 64) * LDA + d];
        float hp0 = __bfloat162float(__ushort_as_bfloat16((unsigned short)(hbits & 0xffffu)))
                  + __bfloat162float(__ushort_as_bfloat16((unsigned short)(lbits & 0xffffu)));
        float hp1 = __bfloat162float(__ushort_as_bfloat16((unsigned short)(hbits >> 16)))
                  + __bfloat162float(__ushort_as_bfloat16((unsigned short)(lbits >> 16)));

        // ---- WMMA: warp = m-tiles {2mg, 2mg+1} x n-tile nt; A,B frags each reused 2x ----
        {
            wmma::fragment<wmma::accumulator, 16, 16, 16, float> acc0, acc1;
            wmma::fill_fragment(acc0, 0.0f);
            wmma::fill_fragment(acc1, 0.0f);
            const __nv_bfloat16* a0p = sA + (mg * 2) * 16 * LDA;
            const __nv_bfloat16* a1p = sA + (mg * 2 + 1) * 16 * LDA;
            const __nv_bfloat16* bhp = sBhi + nt * 16 * LDA;
            const __nv_bfloat16* blp = sBlo + nt * 16 * LDA;
#pragma unroll 8
            for (int kt = 0; kt < 32; ++kt) {
                wmma::fragment<wmma::matrix_a, 16, 16, 16, __nv_bfloat16, wmma::row_major> a0f, a1f;
                wmma::fragment<wmma::matrix_b, 16, 16, 16, __nv_bfloat16, wmma::col_major> bhf, blf;
                wmma::load_matrix_sync(a0f, a0p + kt * 16, LDA);
                wmma::load_matrix_sync(a1f, a1p + kt * 16, LDA);
                wmma::load_matrix_sync(bhf, bhp + kt * 16, LDA);
                wmma::load_matrix_sync(blf, blp + kt * 16, LDA);
                wmma::mma_sync(acc0, a0f, bhf, acc0);
                wmma::mma_sync(acc1, a1f, bhf, acc1);
                wmma::mma_sync(acc0, a0f, blf, acc0);
                wmma::mma_sync(acc1, a1f, blf, acc1);
            }
            wmma::store_matrix_sync(sD + (mg * 2) * 16 * LDD + nt * 16, acc0, LDD, wmma::mem_row_major);
            wmma::store_matrix_sync(sD + (mg * 2 + 1) * 16 * LDD + nt * 16, acc1, LDD, wmma::mem_row_major);
        }
        __syncthreads();

        // ---- gates + zoneout (MUFU-free transcendentals) ----
        if (dir && (1023 - s) < sLen[b] - 1) { c0r = 0.f; c1r = 0.f; }
        const float* dt = &sD[b * LDD];
        const float* db = &sD[(b + 64) * LDD];
        float a_i0 = dt[dd] + db[dd],           a_i1 = dt[dd + 1] + db[dd + 1];
        float a_g0 = dt[8 + dd] + db[8 + dd],   a_g1 = dt[9 + dd] + db[9 + dd];
        float a_f0 = dt[16 + dd] + db[16 + dd], a_f1 = dt[17 + dd] + db[17 + dd];
        float a_o0 = dt[24 + dd] + db[24 + dd], a_o1 = dt[25 + dd] + db[25 + dd];
        float f0 = sigm_fast(pxf.x + a_f0 + 1.f), f1 = sigm_fast(pxf.y + a_f1 + 1.f);
        float o0 = sigm_fast(pxo.x + a_o0), o1 = sigm_fast(pxo.y + a_o1);
        float cn0 = f0 * c0r + sigm_fast(pxi.x + a_i0) * tanh_fast(pxg.x + a_g0);
        float cn1 = f1 * c1r + sigm_fast(pxi.y + a_i1) * tanh_fast(pxg.y + a_g1);
        float hn0 = o0 * tanh_fast(cn0);
        float hn1 = o1 * tanh_fast(cn1);
        float ho0 = (z0 & 1) ? hp0 : hn0;
        float ho1 = (z1 & 1) ? hp1 : hn1;
        c0r = (z0 & 2) ? c0r : cn0;
        c1r = (z1 & 2) ? c1r : cn1;

        // ---- next-step h (bwd reset pre-applied), stored as bf16 hi/lo ----
        float w0 = ho0, w1 = ho1;
        if (dir && (1022 - s) < sLen[b] - 1) { w0 = 0.f; w1 = 0.f; }
        __nv_bfloat16 h0 = __float2bfloat16(w0), h1 = __float2bfloat16(w1);
        __nv_bfloat16 l0 = __float2bfloat16(w0 - __bfloat162float(h0));
        __nv_bfloat16 l1 = __float2bfloat16(w1 - __bfloat162float(h1));
        unsigned char* hw = g_hA[dir][(s + 1) & 1];
        uint32_t hv = (uint32_t)__bfloat16_as_ushort(h0) | ((uint32_t)__bfloat16_as_ushort(h1) << 16);
        uint32_t lv = (uint32_t)__bfloat16_as_ushort(l0) | ((uint32_t)__bfloat16_as_ushort(l1) << 16);
        __stcg((uint32_t*)(hw + (size_t)(b * LDA + d) * 2), hv);
        __stcg((uint32_t*)(hw + (size_t)((b + 64) * LDA + d) * 2), lv);

        // ---- flag-based grid barrier; out store overlapped with poll window ----
        __syncthreads();                               // all h stores issued
        if (s < 1023) {
            if (tid == 0) {
                __threadfence();
                *(volatile unsigned*)&g_flag[dir][cta].v = (unsigned)(s + 1);
            }
            *(float2*)&out[(((size_t)b << 10) + tx) * 1024 + ((size_t)dir << 9) + d] = make_float2(ho0, ho1);
            if (tid < 64) {
                volatile unsigned* f = &g_flag[dir][tid].v;
                while (*f < (unsigned)(s + 1)) __nanosleep(64);
            }
            __syncthreads();
        } else {
            *(float2*)&out[(((size_t)b << 10) + tx) * 1024 + ((size_t)dir << 9) + d] = make_float2(ho0, ho1);
        }
    }
}

// ---------------- launch ----------------
extern "C" void kernel_launch(void* const* d_in, const int* in_sizes, int n_in,
                              void* d_out, int out_size) {
    (void)in_sizes; (void)n_in; (void)out_size;
    const int*   tokens  = (const int*)d_in[0];
    const int*   lengths = (const int*)d_in[1];
    const float* embed   = (const float*)d_in[2];
    const float* Wf      = (const float*)d_in[3];
    const float* bf      = (const float*)d_in[4];
    const float* Wb      = (const float*)d_in[5];
    const float* bb      = (const float*)d_in[6];
    float* out = (float*)d_out;

    cudaFuncSetAttribute(scan_kernel, cudaFuncAttributeMaxDynamicSharedMemorySize, SCAN_SMEM);
    cudaFuncSetAttribute(proj_corr_kernel, cudaFuncAttributeMaxDynamicSharedMemorySize, CORR_SMEM);

    void* hA_ptr = nullptr;
    cudaGetSymbolAddress(&hA_ptr, g_hA);

    rng_setup_kernel<<<1, 128>>>();
    base_kernel<<<dim3(8, 64, 2), 256>>>(embed, Wf, Wb);
    drop_kernel<<<8192, 256>>>(tokens, embed);
    zoneout_kernel<<<(2u * 1024u * 32768u) / 256u, 256>>>();
    cudaMemsetAsync(hA_ptr, 0, (size_t)2 * 2 * A_BYTES);
    proj_corr_kernel<<<dim3(64, 16), 256, CORR_SMEM>>>(tokens, Wf, Wb, bf, bb);
    scan_kernel<<<128, 256, SCAN_SMEM>>>(lengths, Wf, Wb, out);
}

// round 13
// speedup vs baseline: 3.2007x; 1.0689x over previous
#include <cuda_runtime.h>
#include <cuda_bf16.h>
#include <mma.h>
#include <cstdint>
#include <cstddef>

using namespace nvcuda;

// ---------------- device scratch (static, no runtime alloc) ----------------
__device__ float g_preF[(size_t)1024 * 64 * 2048];      // x@Wf[:512]+bf, time-major [t][b][g]
__device__ float g_preB[(size_t)1024 * 64 * 2048];      // x@Wb[:512]+bb
__device__ float g_base[2][256][2048];                  // embed@W[:512] per vocab entry
__device__ uint2 g_dropPack[(size_t)65536 * 128];       // per row: (d, bits(e[tok][d])) dropped entries
__device__ unsigned int g_dropN[65536];                 // per row: dropped count
__device__ uint2 g_kz[2 * 1024];                        // per-step zoneout keys (fwd, bwd)
__device__ uint2 g_kd;                                  // dropout key
// h exchange: two K-blocks per buffer. Block = 128 rows x 264 bf16 (rows 0-63 h_hi, 64-127 h_lo),
// block0 = dims 0-255 (CTAs 0-31), block1 = dims 256-511 (CTAs 32-63).
#define LDAB 264
#define A_BLOCK_BYTES 67584u                            // 128*264*2
__device__ __align__(1024) unsigned char g_hA[2][2][2][67584];
// per-CTA step flags, padded to 128B (one L2 line each)
struct FlagLine { unsigned v; unsigned pad[31]; };
__device__ FlagLine g_flag[2][64];

// ---------------- JAX threefry2x32 (bit-exact, 20 rounds) ----------------
__device__ __forceinline__ uint32_t rotl32(uint32_t x, int r) { return (x << r) | (x >> (32 - r)); }

__device__ __forceinline__ void tf2x32(uint32_t k0, uint32_t k1, uint32_t& x0, uint32_t& x1) {
    uint32_t k2 = k0 ^ k1 ^ 0x1BD11BDAu;
    x0 += k0; x1 += k1;
#define TFR(r) { x0 += x1; x1 = rotl32(x1, r); x1 ^= x0; }
    TFR(13) TFR(15) TFR(26) TFR(6)   x0 += k1; x1 += k2 + 1u;
    TFR(17) TFR(29) TFR(16) TFR(24)  x0 += k2; x1 += k0 + 2u;
    TFR(13) TFR(15) TFR(26) TFR(6)   x0 += k0; x1 += k1 + 3u;
    TFR(17) TFR(29) TFR(16) TFR(24)  x0 += k1; x1 += k2 + 4u;
    TFR(13) TFR(15) TFR(26) TFR(6)   x0 += k2; x1 += k0 + 5u;
#undef TFR
}

__device__ __forceinline__ uint32_t pbits(uint32_t k0, uint32_t k1, uint32_t i) {
    uint32_t x0 = 0u, x1 = i;
    tf2x32(k0, k1, x0, x1);
    return x0 ^ x1;
}

__device__ __forceinline__ float u01(uint32_t bits) {
    return __uint_as_float((bits >> 9) | 0x3f800000u) - 1.0f;
}

// ---------------- MUFU-free transcendentals ----------------
__device__ __forceinline__ float sigm_fast(float x) {
    float t = -x * 1.44269504088896341f;
    t = fminf(fmaxf(t, -126.0f), 126.0f);
    float z = t + 12582912.0f;
    int ii = __float_as_int(z) - 0x4B400000;
    float f = t - (z - 12582912.0f);
    float p =            1.54035303933816e-4f;
    p = fmaf(p, f, 1.33335581464284e-3f);
    p = fmaf(p, f, 9.61812910762848e-3f);
    p = fmaf(p, f, 5.55041086648216e-2f);
    p = fmaf(p, f, 2.40226506959101e-1f);
    p = fmaf(p, f, 6.93147180559945e-1f);
    p = fmaf(p, f, 1.0f);
    float e = p * __int_as_float((ii + 127) << 23);
    float d = 1.0f + e;
    float y = __int_as_float(0x7EF311C3 - __float_as_int(d));
    y = y * (2.0f - d * y);
    y = y * (2.0f - d * y);
    y = y * (2.0f - d * y);
    return y;
}
__device__ __forceinline__ float tanh_fast(float x) {
    return fmaf(2.0f, sigm_fast(2.0f * x), -1.0f);
}

// ---------------- K1: key derivation + flag reset ----------------
__global__ void rng_setup_kernel() {
    int tid = threadIdx.x;
    __shared__ uint32_t s[4];
    if (tid < 128) g_flag[tid >> 6][tid & 63].v = 0u;
    if (tid == 0) {
        uint32_t a, b;
        a = 0u; b = 0u; tf2x32(0u, 42u, a, b); g_kd = make_uint2(a, b);
        a = 0u; b = 1u; tf2x32(0u, 42u, a, b); s[0] = a; s[1] = b;   // kf
        a = 0u; b = 2u; tf2x32(0u, 42u, a, b); s[2] = a; s[3] = b;   // kb
    }
    __syncthreads();
    if (tid < 2) {
        uint32_t k0 = s[tid * 2], k1 = s[tid * 2 + 1];
        for (int t = 0; t < 1024; ++t) {
            uint32_t z0 = 0u, z1 = 0u; tf2x32(k0, k1, z0, z1);
            uint32_t n0 = 0u, n1 = 1u; tf2x32(k0, k1, n0, n1);
            g_kz[tid * 1024 + t] = make_uint2(z0, z1);
            k0 = n0; k1 = n1;
        }
    }
}

// ---------------- K2: vocab base table ----------------
__global__ void __launch_bounds__(256) base_kernel(const float* __restrict__ embed,
                                                   const float* __restrict__ Wf,
                                                   const float* __restrict__ Wb) {
    int dir = blockIdx.z;
    const float* W = dir ? Wb : Wf;
    int g = blockIdx.x * 256 + threadIdx.x;
    int v0 = blockIdx.y * 4;
    float acc0 = 0.f, acc1 = 0.f, acc2 = 0.f, acc3 = 0.f;
#pragma unroll 4
    for (int d = 0; d < 512; ++d) {
        float w = W[(size_t)d * 2048 + g];
        acc0 = fmaf(embed[(size_t)(v0 + 0) * 512 + d], w, acc0);
        acc1 = fmaf(embed[(size_t)(v0 + 1) * 512 + d], w, acc1);
        acc2 = fmaf(embed[(size_t)(v0 + 2) * 512 + d], w, acc2);
        acc3 = fmaf(embed[(size_t)(v0 + 3) * 512 + d], w, acc3);
    }
    g_base[dir][v0 + 0][g] = acc0;
    g_base[dir][v0 + 1][g] = acc1;
    g_base[dir][v0 + 2][g] = acc2;
    g_base[dir][v0 + 3][g] = acc3;
}

// ---------------- K3: dropout lists ----------------
__global__ void __launch_bounds__(256) drop_kernel(const int* __restrict__ tokens,
                                                   const float* __restrict__ embed) {
    unsigned row = (blockIdx.x * 256u + threadIdx.x) >> 5;
    int lane = threadIdx.x & 31;
    uint2 kd = g_kd;
    int tok = tokens[row];
    const float* erow = &embed[(size_t)tok * 512];
    uint2* outp = &g_dropPack[(size_t)row * 128];
    unsigned count = 0;
#pragma unroll 4
    for (int it = 0; it < 16; ++it) {
        int d = it * 32 + lane;
        uint32_t bits = pbits(kd.x, kd.y, row * 512u + (unsigned)d);
        bool dropped = !(u01(bits) < 0.9f);
        unsigned m = __ballot_sync(0xffffffffu, dropped);
        if (dropped) {
            unsigned pos = count + __popc(m & ((1u << lane) - 1u));
            outp[pos] = make_uint2((unsigned)d, __float_as_uint(erow[d]));
        }
        count += __popc(m);
    }
    if (lane == 0) g_dropN[row] = count;
}

// ---------------- K5: projection (base + sparse dropout correction) ----------------
#define CORR_SMEM (512 * 64 * 4)

__global__ void __launch_bounds__(256, 1) proj_corr_kernel(const int* __restrict__ tokens,
                                                           const float* __restrict__ Wf,
                                                           const float* __restrict__ Wb,
                                                           const float* __restrict__ bf,
                                                           const float* __restrict__ bb) {
    extern __shared__ float sW[];
    int dir = blockIdx.x >> 5;
    int slice = blockIdx.x & 31;
    int g0 = slice * 64;
    const float* W = dir ? Wb : Wf;
    const float* bias = dir ? bb : bf;
    float* pre = dir ? g_preB : g_preF;
    const float* base = &g_base[dir][0][0];
    int tid = threadIdx.x;

    for (int i = tid; i < 512 * 64; i += 256)
        sW[i] = W[(size_t)(i >> 6) * 2048 + g0 + (i & 63)];
    __syncthreads();

    int lane = tid & 31, w = tid >> 5;
    float2 bv = *(const float2*)&bias[g0 + lane * 2];
    int rEnd = blockIdx.y * 4096 + 4096;
    for (int r = blockIdx.y * 4096 + w; r < rEnd; r += 8) {
        int tok = tokens[r];
        unsigned n = g_dropN[r];
        const uint2* lst = &g_dropPack[(size_t)r * 128];
        float2 acc = *(const float2*)&base[(size_t)tok * 2048 + g0 + lane * 2];
        for (unsigned j0 = 0; j0 < n; j0 += 32) {
            uint2 e = make_uint2(0u, 0u);
            if (j0 + lane < n) e = __ldcg(&lst[j0 + lane]);
#pragma unroll
            for (int jj = 0; jj < 32; ++jj) {
                unsigned dx = __shfl_sync(0xffffffffu, e.x, jj);
                unsigned dv = __shfl_sync(0xffffffffu, e.y, jj);
                float val = __uint_as_float(dv);
                float2 wv = *(const float2*)&sW[dx * 64 + lane * 2];
                acc.x = fmaf(-val, wv.x, acc.x);
                acc.y = fmaf(-val, wv.y, acc.y);
            }
        }
        int b = r >> 10, t = r & 1023;
        float2 o;
        o.x = fmaf(acc.x, (1.0f / 0.9f), bv.x);
        o.y = fmaf(acc.y, (1.0f / 0.9f), bv.y);
        *(float2*)&pre[(((size_t)t * 64) + b) * 2048 + g0 + lane * 2] = o;
    }
}

// ---------------- K6: persistent bidirectional LSTM scan — WMMA, K-split pipelined exchange ----------------
#define LDB 520
#define SA0_OFF 0
#define SA1_OFF 67584
#define SBHI_OFF (2 * 67584)                        // 135168
#define SBLO_OFF (SBHI_OFF + 32 * LDB * 2)          // 168448
#define SD_OFF   (SBLO_OFF + 32 * LDB * 2)          // 201728
#define LDD 40
#define SCAN_SMEM (SD_OFF + 128 * LDD * 4)          // 222208

__device__ __forceinline__ void wait_par(uint32_t bar, unsigned p) {
    asm volatile(
        "{\n\t.reg .pred P;\n\t"
        "WL_%=:\n\t"
        "mbarrier.try_wait.parity.acquire.cta.shared::cta.b64 P, [%0], %1, 0x989680;\n\t"
        "@P bra WD_%=;\n\t"
        "bra WL_%=;\n\t"
        "WD_%=:\n\t}"
        :: "r"(bar), "r"(p) : "memory");
}
__device__ __forceinline__ void tma_block(uint32_t dst, const unsigned char* src, uint32_t bar) {
    asm volatile("mbarrier.arrive.expect_tx.shared.b64 _, [%0], %1;"
                 :: "r"(bar), "r"(A_BLOCK_BYTES) : "memory");
    asm volatile("cp.async.bulk.shared::cta.global.mbarrier::complete_tx::bytes [%0], [%1], %2, [%3];"
                 :: "r"(dst), "l"(src), "r"(A_BLOCK_BYTES), "r"(bar) : "memory");
}

__global__ void __launch_bounds__(256, 1) scan_kernel(const int* __restrict__ lengths,
                                                      const float* __restrict__ Wf,
                                                      const float* __restrict__ Wb,
                                                      float* __restrict__ out) {
    extern __shared__ unsigned char smem[];
    __nv_bfloat16* sA0  = (__nv_bfloat16*)(smem + SA0_OFF);
    __nv_bfloat16* sA1  = (__nv_bfloat16*)(smem + SA1_OFF);
    __nv_bfloat16* sBhi = (__nv_bfloat16*)(smem + SBHI_OFF);
    __nv_bfloat16* sBlo = (__nv_bfloat16*)(smem + SBLO_OFF);
    float* sD = (float*)(smem + SD_OFF);
    __shared__ int sLen[64];
    __shared__ __align__(8) unsigned long long mbar0, mbar1;

    int dir = blockIdx.x >> 6, cta = blockIdx.x & 63, d0 = cta * 8;
    int tid = threadIdx.x, wid = tid >> 5;
    const float* W = dir ? Wb : Wf;

    uint32_t sA0_addr = (uint32_t)__cvta_generic_to_shared(sA0);
    uint32_t sA1_addr = (uint32_t)__cvta_generic_to_shared(sA1);
    uint32_t bar0 = (uint32_t)__cvta_generic_to_shared(&mbar0);
    uint32_t bar1 = (uint32_t)__cvta_generic_to_shared(&mbar1);
    if (tid == 0) {
        asm volatile("mbarrier.init.shared.b64 [%0], 1;" :: "r"(bar0) : "memory");
        asm volatile("mbarrier.init.shared.b64 [%0], 1;" :: "r"(bar1) : "memory");
    }

    // W slice -> bf16 hi/lo, col-major (k contiguous), one-time
    for (int i = tid; i < 32 * 512; i += 256) {
        int n = i & 31, k = i >> 5;
        float w = W[(size_t)(512 + k) * 2048 + ((n >> 3) << 9) + d0 + (n & 7)];
        __nv_bfloat16 hi = __float2bfloat16(w);
        __nv_bfloat16 lo = __float2bfloat16(w - __bfloat162float(hi));
        sBhi[n * LDB + k] = hi;
        sBlo[n * LDB + k] = lo;
    }
    if (tid < 64) sLen[tid] = lengths[tid];
    __syncthreads();

    // prologue: stage A for step 0 (g_hA pre-zeroed)
    if (tid == 0)  tma_block(sA0_addr, g_hA[dir][0][0], bar0);
    if (tid == 32) tma_block(sA1_addr, g_hA[dir][0][1], bar1);

    int q = tid >> 6, b = tid & 63;
    int dd = q * 2, d = d0 + dd;
    float c0r = 0.f, c1r = 0.f;
    float hp0r = 0.f, hp1r = 0.f;                    // previous staged h (exact, in regs)
    const float* pre = dir ? g_preB : g_preF;
    int mg = wid >> 1, nt = wid & 1;
    int blk = cta >> 5;
    unsigned colw = (unsigned)(d & 255);
    size_t offH = (size_t)(b * LDAB + colw) * 2;
    size_t offL = (size_t)((b + 64) * LDAB + colw) * 2;
    unsigned p0 = (unsigned)(b * 512 + d);

    for (int s = 0; s < 1024; ++s) {
        int tx = dir ? (1023 - s) : s;
        unsigned par = (unsigned)(s & 1);

        // ---- independent prefetch + in-scan zoneout RNG (overlaps TMA) ----
        size_t prow = ((size_t)tx * 64 + b) * 2048 + (size_t)d;
        float2 pxi = *(const float2*)&pre[prow];
        float2 pxg = *(const float2*)&pre[prow + 512];
        float2 pxf = *(const float2*)&pre[prow + 1024];
        float2 pxo = *(const float2*)&pre[prow + 1536];
        uint2 kz = __ldg(&g_kz[dir * 1024 + s]);
        bool kh0 = u01(pbits(kz.x, kz.y, p0)) < 0.1f;
        bool kh1 = u01(pbits(kz.x, kz.y, p0 + 1u)) < 0.1f;
        bool kc0 = u01(pbits(kz.x, kz.y, p0 + 32768u)) < 0.1f;
        bool kc1 = u01(pbits(kz.x, kz.y, p0 + 32769u)) < 0.1f;

        // ---- WMMA over K-halves, pipelined with the two bulk copies ----
        wmma::fragment<wmma::accumulator, 16, 16, 16, float> acc0, acc1;
        wmma::fill_fragment(acc0, 0.0f);
        wmma::fill_fragment(acc1, 0.0f);
        const __nv_bfloat16* bhp = sBhi + nt * 16 * LDB;
        const __nv_bfloat16* blp = sBlo + nt * 16 * LDB;

        wait_par(bar0, par);
        {
            const __nv_bfloat16* a0p = sA0 + (mg * 2) * 16 * LDAB;
            const __nv_bfloat16* a1p = sA0 + (mg * 2 + 1) * 16 * LDAB;
#pragma unroll 4
            for (int kt = 0; kt < 16; ++kt) {
                wmma::fragment<wmma::matrix_a, 16, 16, 16, __nv_bfloat16, wmma::row_major> a0f, a1f;
                wmma::fragment<wmma::matrix_b, 16, 16, 16, __nv_bfloat16, wmma::col_major> bhf, blf;
                wmma::load_matrix_sync(a0f, a0p + kt * 16, LDAB);
                wmma::load_matrix_sync(a1f, a1p + kt * 16, LDAB);
                wmma::load_matrix_sync(bhf, bhp + kt * 16, LDB);
                wmma::load_matrix_sync(blf, blp + kt * 16, LDB);
                wmma::mma_sync(acc0, a0f, bhf, acc0);
                wmma::mma_sync(acc1, a1f, bhf, acc1);
                wmma::mma_sync(acc0, a0f, blf, acc0);
                wmma::mma_sync(acc1, a1f, blf, acc1);
            }
        }
        wait_par(bar1, par);
        {
            const __nv_bfloat16* a0p = sA1 + (mg * 2) * 16 * LDAB;
            const __nv_bfloat16* a1p = sA1 + (mg * 2 + 1) * 16 * LDAB;
#pragma unroll 4
            for (int kt = 0; kt < 16; ++kt) {
                wmma::fragment<wmma::matrix_a, 16, 16, 16, __nv_bfloat16, wmma::row_major> a0f, a1f;
                wmma::fragment<wmma::matrix_b, 16, 16, 16, __nv_bfloat16, wmma::col_major> bhf, blf;
                wmma::load_matrix_sync(a0f, a0p + kt * 16, LDAB);
                wmma::load_matrix_sync(a1f, a1p + kt * 16, LDAB);
                wmma::load_matrix_sync(bhf, bhp + (16 + kt) * 16, LDB);
                wmma::load_matrix_sync(blf, blp + (16 + kt) * 16, LDB);
                wmma::mma_sync(acc0, a0f, bhf, acc0);
                wmma::mma_sync(acc1, a1f, bhf, acc1);
                wmma::mma_sync(acc0, a0f, blf, acc0);
                wmma::mma_sync(acc1, a1f, blf, acc1);
            }
        }
        wmma::store_matrix_sync(sD + (mg * 2) * 16 * LDD + nt * 16, acc0, LDD, wmma::mem_row_major);
        wmma::store_matrix_sync(sD + (mg * 2 + 1) * 16 * LDD + nt * 16, acc1, LDD, wmma::mem_row_major);
        __syncthreads();

        // ---- gates + zoneout ----
        if (dir && (1023 - s) < sLen[b] - 1) { c0r = 0.f; c1r = 0.f; }
        const float* dt = &sD[b * LDD];
        const float* db = &sD[(b + 64) * LDD];
        float a_i0 = dt[dd] + db[dd],           a_i1 = dt[dd + 1] + db[dd + 1];
        float a_g0 = dt[8 + dd] + db[8 + dd],   a_g1 = dt[9 + dd] + db[9 + dd];
        float a_f0 = dt[16 + dd] + db[16 + dd], a_f1 = dt[17 + dd] + db[17 + dd];
        float a_o0 = dt[24 + dd] + db[24 + dd], a_o1 = dt[25 + dd] + db[25 + dd];
        float f0 = sigm_fast(pxf.x + a_f0 + 1.f), f1 = sigm_fast(pxf.y + a_f1 + 1.f);
        float o0 = sigm_fast(pxo.x + a_o0), o1 = sigm_fast(pxo.y + a_o1);
        float cn0 = f0 * c0r + sigm_fast(pxi.x + a_i0) * tanh_fast(pxg.x + a_g0);
        float cn1 = f1 * c1r + sigm_fast(pxi.y + a_i1) * tanh_fast(pxg.y + a_g1);
        float hn0 = o0 * tanh_fast(cn0);
        float hn1 = o1 * tanh_fast(cn1);
        float ho0 = kh0 ? hp0r : hn0;
        float ho1 = kh1 ? hp1r : hn1;
        c0r = kc0 ? c0r : cn0;
        c1r = kc1 ? c1r : cn1;

        // ---- next-step h (bwd reset pre-applied) as bf16 hi/lo into block layout ----
        float w0 = ho0, w1 = ho1;
        if (dir && (1022 - s) < sLen[b] - 1) { w0 = 0.f; w1 = 0.f; }
        hp0r = w0; hp1r = w1;
        __nv_bfloat16 h0 = __float2bfloat16(w0), h1 = __float2bfloat16(w1);
        __nv_bfloat16 l0 = __float2bfloat16(w0 - __bfloat162float(h0));
        __nv_bfloat16 l1 = __float2bfloat16(w1 - __bfloat162float(h1));
        unsigned char* hw = g_hA[dir][(s + 1) & 1][blk];
        uint32_t hv = (uint32_t)__bfloat16_as_ushort(h0) | ((uint32_t)__bfloat16_as_ushort(h1) << 16);
        uint32_t lv = (uint32_t)__bfloat16_as_ushort(l0) | ((uint32_t)__bfloat16_as_ushort(l1) << 16);
        __stcg((uint32_t*)(hw + offH), hv);
        __stcg((uint32_t*)(hw + offL), lv);

        __syncthreads();                               // all h stores + sD reads complete
        if (s < 1023) {
            if (tid == 0) {
                __threadfence();
                *(volatile unsigned*)&g_flag[dir][cta].v = (unsigned)(s + 1);
            }
            *(float2*)&out[(((size_t)b << 10) + tx) * 1024 + ((size_t)dir << 9) + d] = make_float2(ho0, ho1);
            if (tid < 32) {                            // warp0: block0 producers (CTAs 0-31)
                volatile unsigned* f = &g_flag[dir][tid].v;
                while (*f < (unsigned)(s + 1)) __nanosleep(64);
                __syncwarp();
                if (tid == 0) tma_block(sA0_addr, g_hA[dir][(s + 1) & 1][0], bar0);
            } else if (tid < 64) {                     // warp1: block1 producers (CTAs 32-63)
                volatile unsigned* f = &g_flag[dir][tid].v;
                while (*f < (unsigned)(s + 1)) __nanosleep(64);
                __syncwarp();
                if (tid == 32) tma_block(sA1_addr, g_hA[dir][(s + 1) & 1][1], bar1);
            }
            // no trailing __syncthreads: remaining warps block on mbarrier at loop top
        } else {
            *(float2*)&out[(((size_t)b << 10) + tx) * 1024 + ((size_t)dir << 9) + d] = make_float2(ho0, ho1);
        }
    }
}

// ---------------- launch ----------------
extern "C" void kernel_launch(void* const* d_in, const int* in_sizes, int n_in,
                              void* d_out, int out_size) {
    (void)in_sizes; (void)n_in; (void)out_size;
    const int*   tokens  = (const int*)d_in[0];
    const int*   lengths = (const int*)d_in[1];
    const float* embed   = (const float*)d_in[2];
    const float* Wf      = (const float*)d_in[3];
    const float* bf      = (const float*)d_in[4];
    const float* Wb      = (const float*)d_in[5];
    const float* bb      = (const float*)d_in[6];
    float* out = (float*)d_out;

    cudaFuncSetAttribute(scan_kernel, cudaFuncAttributeMaxDynamicSharedMemorySize, SCAN_SMEM);
    cudaFuncSetAttribute(proj_corr_kernel, cudaFuncAttributeMaxDynamicSharedMemorySize, CORR_SMEM);

    void* hA_ptr = nullptr;
    cudaGetSymbolAddress(&hA_ptr, g_hA);

    rng_setup_kernel<<<1, 128>>>();
    base_kernel<<<dim3(8, 64, 2), 256>>>(embed, Wf, Wb);
    drop_kernel<<<8192, 256>>>(tokens, embed);
    cudaMemsetAsync(hA_ptr, 0, (size_t)2 * 2 * 2 * 67584);
    proj_corr_kernel<<<dim3(64, 16), 256, CORR_SMEM>>>(tokens, Wf, Wb, bf, bb);
    scan_kernel<<<128, 256, SCAN_SMEM>>>(lengths, Wf, Wb, out);
}

// round 14
// speedup vs baseline: 3.2660x; 1.0204x over previous
#include <cuda_runtime.h>
#include <cuda_bf16.h>
#include <mma.h>
#include <cstdint>
#include <cstddef>

using namespace nvcuda;

// ---------------- device scratch (static, no runtime alloc) ----------------
__device__ float g_preF[(size_t)1024 * 64 * 2048];      // x@Wf[:512]+bf, time-major [t][b][g]
__device__ float g_preB[(size_t)1024 * 64 * 2048];      // x@Wb[:512]+bb
__device__ float g_base[2][256][2048];                  // embed@W[:512] per vocab entry
__device__ uint2 g_dropPack[(size_t)65536 * 128];       // per row: (d, bits(e[tok][d])) dropped entries
__device__ unsigned int g_dropN[65536];                 // per row: dropped count
__device__ uint2 g_kz[2 * 1024];                        // per-step zoneout keys (fwd, bwd)
__device__ uint2 g_kd;                                  // dropout key
// h exchange: 4 K-blocks per buffer. Block = 128 rows x 136 bf16 (rows 0-63 h_hi, 64-127 h_lo),
// block j = dims [128j, 128j+128), produced by CTAs 16j..16j+15.
#define LDAB 136
#define A_BLOCK_BYTES 34816u                            // 128*136*2
__device__ __align__(1024) unsigned char g_hA[2][2][4][34816];
// per-CTA step flags, padded to 128B (one L2 line each)
struct FlagLine { unsigned v; unsigned pad[31]; };
__device__ FlagLine g_flag[2][64];

// ---------------- JAX threefry2x32 (bit-exact, 20 rounds) ----------------
__device__ __forceinline__ uint32_t rotl32(uint32_t x, int r) { return (x << r) | (x >> (32 - r)); }

__device__ __forceinline__ void tf2x32(uint32_t k0, uint32_t k1, uint32_t& x0, uint32_t& x1) {
    uint32_t k2 = k0 ^ k1 ^ 0x1BD11BDAu;
    x0 += k0; x1 += k1;
#define TFR(r) { x0 += x1; x1 = rotl32(x1, r); x1 ^= x0; }
    TFR(13) TFR(15) TFR(26) TFR(6)   x0 += k1; x1 += k2 + 1u;
    TFR(17) TFR(29) TFR(16) TFR(24)  x0 += k2; x1 += k0 + 2u;
    TFR(13) TFR(15) TFR(26) TFR(6)   x0 += k0; x1 += k1 + 3u;
    TFR(17) TFR(29) TFR(16) TFR(24)  x0 += k1; x1 += k2 + 4u;
    TFR(13) TFR(15) TFR(26) TFR(6)   x0 += k2; x1 += k0 + 5u;
#undef TFR
}

__device__ __forceinline__ uint32_t pbits(uint32_t k0, uint32_t k1, uint32_t i) {
    uint32_t x0 = 0u, x1 = i;
    tf2x32(k0, k1, x0, x1);
    return x0 ^ x1;
}

__device__ __forceinline__ float u01(uint32_t bits) {
    return __uint_as_float((bits >> 9) | 0x3f800000u) - 1.0f;
}

// ---------------- MUFU-free transcendentals ----------------
__device__ __forceinline__ float sigm_fast(float x) {
    float t = -x * 1.44269504088896341f;
    t = fminf(fmaxf(t, -126.0f), 126.0f);
    float z = t + 12582912.0f;
    int ii = __float_as_int(z) - 0x4B400000;
    float f = t - (z - 12582912.0f);
    float p =            1.54035303933816e-4f;
    p = fmaf(p, f, 1.33335581464284e-3f);
    p = fmaf(p, f, 9.61812910762848e-3f);
    p = fmaf(p, f, 5.55041086648216e-2f);
    p = fmaf(p, f, 2.40226506959101e-1f);
    p = fmaf(p, f, 6.93147180559945e-1f);
    p = fmaf(p, f, 1.0f);
    float e = p * __int_as_float((ii + 127) << 23);
    float d = 1.0f + e;
    float y = __int_as_float(0x7EF311C3 - __float_as_int(d));
    y = y * (2.0f - d * y);
    y = y * (2.0f - d * y);
    y = y * (2.0f - d * y);
    return y;
}
__device__ __forceinline__ float tanh_fast(float x) {
    return fmaf(2.0f, sigm_fast(2.0f * x), -1.0f);
}

// ---------------- K1: key derivation + flag reset ----------------
__global__ void rng_setup_kernel() {
    int tid = threadIdx.x;
    __shared__ uint32_t s[4];
    if (tid < 128) g_flag[tid >> 6][tid & 63].v = 0u;
    if (tid == 0) {
        uint32_t a, b;
        a = 0u; b = 0u; tf2x32(0u, 42u, a, b); g_kd = make_uint2(a, b);
        a = 0u; b = 1u; tf2x32(0u, 42u, a, b); s[0] = a; s[1] = b;   // kf
        a = 0u; b = 2u; tf2x32(0u, 42u, a, b); s[2] = a; s[3] = b;   // kb
    }
    __syncthreads();
    if (tid < 2) {
        uint32_t k0 = s[tid * 2], k1 = s[tid * 2 + 1];
        for (int t = 0; t < 1024; ++t) {
            uint32_t z0 = 0u, z1 = 0u; tf2x32(k0, k1, z0, z1);
            uint32_t n0 = 0u, n1 = 1u; tf2x32(k0, k1, n0, n1);
            g_kz[tid * 1024 + t] = make_uint2(z0, z1);
            k0 = n0; k1 = n1;
        }
    }
}

// ---------------- K2: vocab base table ----------------
__global__ void __launch_bounds__(256) base_kernel(const float* __restrict__ embed,
                                                   const float* __restrict__ Wf,
                                                   const float* __restrict__ Wb) {
    int dir = blockIdx.z;
    const float* W = dir ? Wb : Wf;
    int g = blockIdx.x * 256 + threadIdx.x;
    int v0 = blockIdx.y * 4;
    float acc0 = 0.f, acc1 = 0.f, acc2 = 0.f, acc3 = 0.f;
#pragma unroll 4
    for (int d = 0; d < 512; ++d) {
        float w = W[(size_t)d * 2048 + g];
        acc0 = fmaf(embed[(size_t)(v0 + 0) * 512 + d], w, acc0);
        acc1 = fmaf(embed[(size_t)(v0 + 1) * 512 + d], w, acc1);
        acc2 = fmaf(embed[(size_t)(v0 + 2) * 512 + d], w, acc2);
        acc3 = fmaf(embed[(size_t)(v0 + 3) * 512 + d], w, acc3);
    }
    g_base[dir][v0 + 0][g] = acc0;
    g_base[dir][v0 + 1][g] = acc1;
    g_base[dir][v0 + 2][g] = acc2;
    g_base[dir][v0 + 3][g] = acc3;
}

// ---------------- K3: dropout lists ----------------
__global__ void __launch_bounds__(256) drop_kernel(const int* __restrict__ tokens,
                                                   const float* __restrict__ embed) {
    unsigned row = (blockIdx.x * 256u + threadIdx.x) >> 5;
    int lane = threadIdx.x & 31;
    uint2 kd = g_kd;
    int tok = tokens[row];
    const float* erow = &embed[(size_t)tok * 512];
    uint2* outp = &g_dropPack[(size_t)row * 128];
    unsigned count = 0;
#pragma unroll 4
    for (int it = 0; it < 16; ++it) {
        int d = it * 32 + lane;
        uint32_t bits = pbits(kd.x, kd.y, row * 512u + (unsigned)d);
        bool dropped = !(u01(bits) < 0.9f);
        unsigned m = __ballot_sync(0xffffffffu, dropped);
        if (dropped) {
            unsigned pos = count + __popc(m & ((1u << lane) - 1u));
            outp[pos] = make_uint2((unsigned)d, __float_as_uint(erow[d]));
        }
        count += __popc(m);
    }
    if (lane == 0) g_dropN[row] = count;
}

// ---------------- K5: projection (base + sparse dropout correction) ----------------
#define CORR_SMEM (512 * 64 * 4)

__global__ void __launch_bounds__(256, 1) proj_corr_kernel(const int* __restrict__ tokens,
                                                           const float* __restrict__ Wf,
                                                           const float* __restrict__ Wb,
                                                           const float* __restrict__ bf,
                                                           const float* __restrict__ bb) {
    extern __shared__ float sW[];
    int dir = blockIdx.x >> 5;
    int slice = blockIdx.x & 31;
    int g0 = slice * 64;
    const float* W = dir ? Wb : Wf;
    const float* bias = dir ? bb : bf;
    float* pre = dir ? g_preB : g_preF;
    const float* base = &g_base[dir][0][0];
    int tid = threadIdx.x;

    for (int i = tid; i < 512 * 64; i += 256)
        sW[i] = W[(size_t)(i >> 6) * 2048 + g0 + (i & 63)];
    __syncthreads();

    int lane = tid & 31, w = tid >> 5;
    float2 bv = *(const float2*)&bias[g0 + lane * 2];
    int rEnd = blockIdx.y * 4096 + 4096;
    for (int r = blockIdx.y * 4096 + w; r < rEnd; r += 8) {
        int tok = tokens[r];
        unsigned n = g_dropN[r];
        const uint2* lst = &g_dropPack[(size_t)r * 128];
        float2 acc = *(const float2*)&base[(size_t)tok * 2048 + g0 + lane * 2];
        for (unsigned j0 = 0; j0 < n; j0 += 32) {
            uint2 e = make_uint2(0u, 0u);
            if (j0 + lane < n) e = __ldcg(&lst[j0 + lane]);
#pragma unroll
            for (int jj = 0; jj < 32; ++jj) {
                unsigned dx = __shfl_sync(0xffffffffu, e.x, jj);
                unsigned dv = __shfl_sync(0xffffffffu, e.y, jj);
                float val = __uint_as_float(dv);
                float2 wv = *(const float2*)&sW[dx * 64 + lane * 2];
                acc.x = fmaf(-val, wv.x, acc.x);
                acc.y = fmaf(-val, wv.y, acc.y);
            }
        }
        int b = r >> 10, t = r & 1023;
        float2 o;
        o.x = fmaf(acc.x, (1.0f / 0.9f), bv.x);
        o.y = fmaf(acc.y, (1.0f / 0.9f), bv.y);
        *(float2*)&pre[(((size_t)t * 64) + b) * 2048 + g0 + lane * 2] = o;
    }
}

// ---------------- K6: persistent bidirectional LSTM scan ----------------
// 3-product split: D = [h_hi;h_lo] @ W_hi  (+)  h_hi @ W_lo  (lo*lo dropped, ~2^-18).
// 4-block K-pipeline: block j (128 dims) has its own mbarrier + 16-flag poll group.
#define LDB 520
#define SA_OFF   0                                   // 4 blocks x 34816 = 139264
#define SBHI_OFF 139264
#define SBLO_OFF (SBHI_OFF + 32 * LDB * 2)           // 172544
#define SD_OFF   (SBLO_OFF + 32 * LDB * 2)           // 205824
#define LDD 40
#define SCAN_SMEM (SD_OFF + 128 * LDD * 4)           // 226304
#define A_BLK_ELEMS (128 * LDAB)                     // 17408

__device__ __forceinline__ void wait_par(uint32_t bar, unsigned p) {
    asm volatile(
        "{\n\t.reg .pred P;\n\t"
        "WL_%=:\n\t"
        "mbarrier.try_wait.parity.acquire.cta.shared::cta.b64 P, [%0], %1, 0x989680;\n\t"
        "@P bra WD_%=;\n\t"
        "bra WL_%=;\n\t"
        "WD_%=:\n\t}"
        :: "r"(bar), "r"(p) : "memory");
}
__device__ __forceinline__ void tma_block(uint32_t dst, const unsigned char* src, uint32_t bar) {
    asm volatile("mbarrier.arrive.expect_tx.shared.b64 _, [%0], %1;"
                 :: "r"(bar), "r"(A_BLOCK_BYTES) : "memory");
    asm volatile("cp.async.bulk.shared::cta.global.mbarrier::complete_tx::bytes [%0], [%1], %2, [%3];"
                 :: "r"(dst), "l"(src), "r"(A_BLOCK_BYTES), "r"(bar) : "memory");
}

__global__ void __launch_bounds__(256, 1) scan_kernel(const int* __restrict__ lengths,
                                                      const float* __restrict__ Wf,
                                                      const float* __restrict__ Wb,
                                                      float* __restrict__ out) {
    extern __shared__ unsigned char smem[];
    __nv_bfloat16* sA   = (__nv_bfloat16*)(smem + SA_OFF);
    __nv_bfloat16* sBhi = (__nv_bfloat16*)(smem + SBHI_OFF);
    __nv_bfloat16* sBlo = (__nv_bfloat16*)(smem + SBLO_OFF);
    float* sD  = (float*)(smem + SD_OFF);
    float* sD2 = (float*)(smem + SA_OFF);            // scratch: reuses block0 A region post-consumption
    __shared__ int sLen[64];
    __shared__ __align__(8) unsigned long long mbars[4];

    int dir = blockIdx.x >> 6, cta = blockIdx.x & 63, d0 = cta * 8;
    int tid = threadIdx.x, wid = tid >> 5, lane = tid & 31;
    const float* W = dir ? Wb : Wf;

    uint32_t sA_addr = (uint32_t)__cvta_generic_to_shared(sA);
    uint32_t bar[4];
#pragma unroll
    for (int j = 0; j < 4; ++j) bar[j] = (uint32_t)__cvta_generic_to_shared(&mbars[j]);
    if (tid < 4)
        asm volatile("mbarrier.init.shared.b64 [%0], 1;" :: "r"(bar[tid]) : "memory");

    // W slice -> bf16 hi/lo, col-major (k contiguous), one-time
    for (int i = tid; i < 32 * 512; i += 256) {
        int n = i & 31, k = i >> 5;
        float w = W[(size_t)(512 + k) * 2048 + ((n >> 3) << 9) + d0 + (n & 7)];
        __nv_bfloat16 hi = __float2bfloat16(w);
        __nv_bfloat16 lo = __float2bfloat16(w - __bfloat162float(hi));
        sBhi[n * LDB + k] = hi;
        sBlo[n * LDB + k] = lo;
    }
    if (tid < 64) sLen[tid] = lengths[tid];
    __syncthreads();

    // prologue: stage all 4 A blocks for step 0 (g_hA pre-zeroed)
    if (tid < 4) tma_block(sA_addr + (unsigned)tid * A_BLOCK_BYTES, g_hA[dir][0][tid], bar[tid]);

    int q = tid >> 6, b = tid & 63;
    int dd = q * 2, d = d0 + dd;
    float c0r = 0.f, c1r = 0.f;
    float hp0r = 0.f, hp1r = 0.f;
    const float* pre = dir ? g_preB : g_preF;
    int mg = wid & 3, nt = wid >> 2;                 // warp: P1 m-tiles {2mg,2mg+1}, n-tile nt
    bool isHiWarp = (mg < 2);                        // mg 0,1 -> A rows 0-63 (h_hi): carries P2
    int blk = cta >> 4;
    unsigned colw = (unsigned)(d & 127);
    size_t offH = (size_t)(b * LDAB + colw) * 2;
    size_t offL = (size_t)((b + 64) * LDAB + colw) * 2;
    unsigned p0 = (unsigned)(b * 512 + d);

    for (int s = 0; s < 1024; ++s) {
        int tx = dir ? (1023 - s) : s;
        unsigned par = (unsigned)(s & 1);

        // ---- independent prefetch + zoneout RNG (overlaps TMA) ----
        size_t prow = ((size_t)tx * 64 + b) * 2048 + (size_t)d;
        float2 pxi = *(const float2*)&pre[prow];
        float2 pxg = *(const float2*)&pre[prow + 512];
        float2 pxf = *(const float2*)&pre[prow + 1024];
        float2 pxo = *(const float2*)&pre[prow + 1536];
        uint2 kz = __ldg(&g_kz[dir * 1024 + s]);
        bool kh0 = u01(pbits(kz.x, kz.y, p0)) < 0.1f;
        bool kh1 = u01(pbits(kz.x, kz.y, p0 + 1u)) < 0.1f;
        bool kc0 = u01(pbits(kz.x, kz.y, p0 + 32768u)) < 0.1f;
        bool kc1 = u01(pbits(kz.x, kz.y, p0 + 32769u)) < 0.1f;

        // ---- WMMA over 4 K-blocks, each gated by its own mbarrier ----
        wmma::fragment<wmma::accumulator, 16, 16, 16, float> acc0, acc1, acc2, acc3;
        wmma::fill_fragment(acc0, 0.0f);
        wmma::fill_fragment(acc1, 0.0f);
        if (isHiWarp) { wmma::fill_fragment(acc2, 0.0f); wmma::fill_fragment(acc3, 0.0f); }
        const __nv_bfloat16* bh_base = sBhi + nt * 16 * LDB;
        const __nv_bfloat16* bl_base = sBlo + nt * 16 * LDB;

#pragma unroll 1
        for (int bk = 0; bk < 4; ++bk) {
            wait_par(bar[bk], par);
            const __nv_bfloat16* a0p = sA + bk * A_BLK_ELEMS + (mg * 32) * LDAB;
            const __nv_bfloat16* a1p = a0p + 16 * LDAB;
            const __nv_bfloat16* bhp = bh_base + bk * 128;
            const __nv_bfloat16* blp = bl_base + bk * 128;
#pragma unroll 4
            for (int kt = 0; kt < 8; ++kt) {
                wmma::fragment<wmma::matrix_a, 16, 16, 16, __nv_bfloat16, wmma::row_major> a0f, a1f;
                wmma::fragment<wmma::matrix_b, 16, 16, 16, __nv_bfloat16, wmma::col_major> bhf;
                wmma::load_matrix_sync(a0f, a0p + kt * 16, LDAB);
                wmma::load_matrix_sync(a1f, a1p + kt * 16, LDAB);
                wmma::load_matrix_sync(bhf, bhp + kt * 16, LDB);
                wmma::mma_sync(acc0, a0f, bhf, acc0);
                wmma::mma_sync(acc1, a1f, bhf, acc1);
                if (isHiWarp) {
                    wmma::fragment<wmma::matrix_b, 16, 16, 16, __nv_bfloat16, wmma::col_major> blf;
                    wmma::load_matrix_sync(blf, blp + kt * 16, LDB);
                    wmma::mma_sync(acc2, a0f, blf, acc2);
                    wmma::mma_sync(acc3, a1f, blf, acc3);
                }
            }
        }
        wmma::store_matrix_sync(sD + (mg * 2) * 16 * LDD + nt * 16, acc0, LDD, wmma::mem_row_major);
        wmma::store_matrix_sync(sD + (mg * 2 + 1) * 16 * LDD + nt * 16, acc1, LDD, wmma::mem_row_major);
        __syncthreads();                               // A consumed by all warps; sD complete
        if (isHiWarp) {
            wmma::store_matrix_sync(sD2 + (mg * 2) * 16 * LDD + nt * 16, acc2, LDD, wmma::mem_row_major);
            wmma::store_matrix_sync(sD2 + (mg * 2 + 1) * 16 * LDD + nt * 16, acc3, LDD, wmma::mem_row_major);
        }
        __syncthreads();

        // ---- gates + zoneout ----
        if (dir && (1023 - s) < sLen[b] - 1) { c0r = 0.f; c1r = 0.f; }
        const float* dt = &sD[b * LDD];
        const float* db = &sD[(b + 64) * LDD];
        const float* d2 = &sD2[b * LDD];
        float a_i0 = dt[dd] + db[dd] + d2[dd];
        float a_i1 = dt[dd + 1] + db[dd + 1] + d2[dd + 1];
        float a_g0 = dt[8 + dd] + db[8 + dd] + d2[8 + dd];
        float a_g1 = dt[9 + dd] + db[9 + dd] + d2[9 + dd];
        float a_f0 = dt[16 + dd] + db[16 + dd] + d2[16 + dd];
        float a_f1 = dt[17 + dd] + db[17 + dd] + d2[17 + dd];
        float a_o0 = dt[24 + dd] + db[24 + dd] + d2[24 + dd];
        float a_o1 = dt[25 + dd] + db[25 + dd] + d2[25 + dd];
        float f0 = sigm_fast(pxf.x + a_f0 + 1.f), f1 = sigm_fast(pxf.y + a_f1 + 1.f);
        float o0 = sigm_fast(pxo.x + a_o0), o1 = sigm_fast(pxo.y + a_o1);
        float cn0 = f0 * c0r + sigm_fast(pxi.x + a_i0) * tanh_fast(pxg.x + a_g0);
        float cn1 = f1 * c1r + sigm_fast(pxi.y + a_i1) * tanh_fast(pxg.y + a_g1);
        float hn0 = o0 * tanh_fast(cn0);
        float hn1 = o1 * tanh_fast(cn1);
        float ho0 = kh0 ? hp0r : hn0;
        float ho1 = kh1 ? hp1r : hn1;
        c0r = kc0 ? c0r : cn0;
        c1r = kc1 ? c1r : cn1;

        // ---- next-step h (bwd reset pre-applied) as bf16 hi/lo into block layout ----
        float w0 = ho0, w1 = ho1;
        if (dir && (1022 - s) < sLen[b] - 1) { w0 = 0.f; w1 = 0.f; }
        hp0r = w0; hp1r = w1;
        __nv_bfloat16 h0 = __float2bfloat16(w0), h1 = __float2bfloat16(w1);
        __nv_bfloat16 l0 = __float2bfloat16(w0 - __bfloat162float(h0));
        __nv_bfloat16 l1 = __float2bfloat16(w1 - __bfloat162float(h1));
        unsigned char* hw = g_hA[dir][(s + 1) & 1][blk];
        uint32_t hv = (uint32_t)__bfloat16_as_ushort(h0) | ((uint32_t)__bfloat16_as_ushort(h1) << 16);
        uint32_t lv = (uint32_t)__bfloat16_as_ushort(l0) | ((uint32_t)__bfloat16_as_ushort(l1) << 16);
        __stcg((uint32_t*)(hw + offH), hv);
        __stcg((uint32_t*)(hw + offL), lv);

        __syncthreads();                               // all h stores + sD/sD2 reads complete
        if (s < 1023) {
            if (tid == 0) {
                __threadfence();
                *(volatile unsigned*)&g_flag[dir][cta].v = (unsigned)(s + 1);
            }
            *(float2*)&out[(((size_t)b << 10) + tx) * 1024 + ((size_t)dir << 9) + d] = make_float2(ho0, ho1);
            if (wid < 4) {                             // warp j: poll group j (flags 16j..16j+15)
                if (lane < 16) {
                    volatile unsigned* f = &g_flag[dir][wid * 16 + lane].v;
                    while (*f < (unsigned)(s + 1)) __nanosleep(64);
                }
                __syncwarp();
                if (lane == 0)
                    tma_block(sA_addr + (unsigned)wid * A_BLOCK_BYTES,
                              g_hA[dir][(s + 1) & 1][wid], bar[wid]);
            }
            // warps 4-7 fall through; they block on bar[0] at next loop top
        } else {
            *(float2*)&out[(((size_t)b << 10) + tx) * 1024 + ((size_t)dir << 9) + d] = make_float2(ho0, ho1);
        }
    }
}

// ---------------- launch ----------------
extern "C" void kernel_launch(void* const* d_in, const int* in_sizes, int n_in,
                              void* d_out, int out_size) {
    (void)in_sizes; (void)n_in; (void)out_size;
    const int*   tokens  = (const int*)d_in[0];
    const int*   lengths = (const int*)d_in[1];
    const float* embed   = (const float*)d_in[2];
    const float* Wf      = (const float*)d_in[3];
    const float* bf      = (const float*)d_in[4];
    const float* Wb      = (const float*)d_in[5];
    const float* bb      = (const float*)d_in[6];
    float* out = (float*)d_out;

    cudaFuncSetAttribute(scan_kernel, cudaFuncAttributeMaxDynamicSharedMemorySize, SCAN_SMEM);
    cudaFuncSetAttribute(proj_corr_kernel, cudaFuncAttributeMaxDynamicSharedMemorySize, CORR_SMEM);

    void* hA_ptr = nullptr;
    cudaGetSymbolAddress(&hA_ptr, g_hA);

    rng_setup_kernel<<<1, 128>>>();
    base_kernel<<<dim3(8, 64, 2), 256>>>(embed, Wf, Wb);
    drop_kernel<<<8192, 256>>>(tokens, embed);
    cudaMemsetAsync(hA_ptr, 0, (size_t)2 * 2 * 4 * 34816);
    proj_corr_kernel<<<dim3(64, 16), 256, CORR_SMEM>>>(tokens, Wf, Wb, bf, bb);
    scan_kernel<<<128, 256, SCAN_SMEM>>>(lengths, Wf, Wb, out);
}

// round 15
// speedup vs baseline: 3.3914x; 1.0384x over previous
#include <cuda_runtime.h>
#include <cuda_bf16.h>
#include <mma.h>
#include <cstdint>
#include <cstddef>

using namespace nvcuda;

// ---------------- device scratch (static, no runtime alloc) ----------------
__device__ float g_preF[(size_t)1024 * 64 * 2048];      // x@Wf[:512]+bf, time-major [t][b][g]
__device__ float g_preB[(size_t)1024 * 64 * 2048];      // x@Wb[:512]+bb
__device__ float g_base[2][256][2048];                  // embed@W[:512] per vocab entry
__device__ uint2 g_dropPack[(size_t)65536 * 128];       // per row: (d, bits(e[tok][d])) dropped entries
__device__ unsigned int g_dropN[65536];                 // per row: dropped count
__device__ uint2 g_kz[2 * 1024];                        // per-step zoneout keys (fwd, bwd)
__device__ uint2 g_kd;                                  // dropout key
// h exchange: 4 K-blocks per buffer. Block = 128 rows x 136 bf16 (rows 0-63 h_hi, 64-127 h_lo)
#define LDAB 136
#define A_BLOCK_BYTES 34816u
__device__ __align__(1024) unsigned char g_hA[2][2][4][34816];
// per-CTA step flags, padded to 128B
struct FlagLine { unsigned v; unsigned pad[31]; };
__device__ FlagLine g_flag[2][64];
// time-major output scratch: [t][dir][d][b]  (coalesced stores from the scan)
__device__ float g_outS[(size_t)1024 * 2 * 512 * 64];

// ---------------- JAX threefry2x32 (bit-exact, 20 rounds) ----------------
__device__ __forceinline__ uint32_t rotl32(uint32_t x, int r) { return (x << r) | (x >> (32 - r)); }

__device__ __forceinline__ void tf2x32(uint32_t k0, uint32_t k1, uint32_t& x0, uint32_t& x1) {
    uint32_t k2 = k0 ^ k1 ^ 0x1BD11BDAu;
    x0 += k0; x1 += k1;
#define TFR(r) { x0 += x1; x1 = rotl32(x1, r); x1 ^= x0; }
    TFR(13) TFR(15) TFR(26) TFR(6)   x0 += k1; x1 += k2 + 1u;
    TFR(17) TFR(29) TFR(16) TFR(24)  x0 += k2; x1 += k0 + 2u;
    TFR(13) TFR(15) TFR(26) TFR(6)   x0 += k0; x1 += k1 + 3u;
    TFR(17) TFR(29) TFR(16) TFR(24)  x0 += k1; x1 += k2 + 4u;
    TFR(13) TFR(15) TFR(26) TFR(6)   x0 += k2; x1 += k0 + 5u;
#undef TFR
}

__device__ __forceinline__ uint32_t pbits(uint32_t k0, uint32_t k1, uint32_t i) {
    uint32_t x0 = 0u, x1 = i;
    tf2x32(k0, k1, x0, x1);
    return x0 ^ x1;
}

__device__ __forceinline__ float u01(uint32_t bits) {
    return __uint_as_float((bits >> 9) | 0x3f800000u) - 1.0f;
}

// ---------------- MUFU-free transcendentals ----------------
__device__ __forceinline__ float sigm_fast(float x) {
    float t = -x * 1.44269504088896341f;
    t = fminf(fmaxf(t, -126.0f), 126.0f);
    float z = t + 12582912.0f;
    int ii = __float_as_int(z) - 0x4B400000;
    float f = t - (z - 12582912.0f);
    float p =            1.54035303933816e-4f;
    p = fmaf(p, f, 1.33335581464284e-3f);
    p = fmaf(p, f, 9.61812910762848e-3f);
    p = fmaf(p, f, 5.55041086648216e-2f);
    p = fmaf(p, f, 2.40226506959101e-1f);
    p = fmaf(p, f, 6.93147180559945e-1f);
    p = fmaf(p, f, 1.0f);
    float e = p * __int_as_float((ii + 127) << 23);
    float d = 1.0f + e;
    float y = __int_as_float(0x7EF311C3 - __float_as_int(d));
    y = y * (2.0f - d * y);
    y = y * (2.0f - d * y);
    y = y * (2.0f - d * y);
    return y;
}
__device__ __forceinline__ float tanh_fast(float x) {
    return fmaf(2.0f, sigm_fast(2.0f * x), -1.0f);
}

// ---------------- K1: setup — keys, flags, zero g_hA ----------------
__global__ void setup_kernel() {
    int tid = threadIdx.x;
    if (blockIdx.x == 0) {
        __shared__ uint32_t s[4];
        if (tid < 128) g_flag[tid >> 6][tid & 63].v = 0u;
        if (tid == 0) {
            uint32_t a, b;
            a = 0u; b = 0u; tf2x32(0u, 42u, a, b); g_kd = make_uint2(a, b);
            a = 0u; b = 1u; tf2x32(0u, 42u, a, b); s[0] = a; s[1] = b;   // kf
            a = 0u; b = 2u; tf2x32(0u, 42u, a, b); s[2] = a; s[3] = b;   // kb
        }
        __syncthreads();
        if (tid < 2) {
            uint32_t k0 = s[tid * 2], k1 = s[tid * 2 + 1];
            for (int t = 0; t < 1024; ++t) {
                uint32_t z0 = 0u, z1 = 0u; tf2x32(k0, k1, z0, z1);
                uint32_t n0 = 0u, n1 = 1u; tf2x32(k0, k1, n0, n1);
                g_kz[tid * 1024 + t] = make_uint2(z0, z1);
                k0 = n0; k1 = n1;
            }
        }
    }
    // all blocks: zero g_hA (557056 B = 139264 u32)
    uint32_t* hA = (uint32_t*)&g_hA[0][0][0][0];
    for (unsigned i = blockIdx.x * 256u + tid; i < 139264u; i += gridDim.x * 256u)
        hA[i] = 0u;
}

// ---------------- K2: base table + dropout lists (fused) ----------------
__global__ void __launch_bounds__(256) basedrop_kernel(const int* __restrict__ tokens,
                                                       const float* __restrict__ embed,
                                                       const float* __restrict__ Wf,
                                                       const float* __restrict__ Wb) {
    int bid = blockIdx.x;
    int tid = threadIdx.x;
    if (bid < 1024) {
        // base part: bid = dir*512 + v0blk*8 + gblk
        int dir = bid >> 9;
        int rem = bid & 511;
        int gx = rem & 7, v0 = (rem >> 3) * 4;
        const float* W = dir ? Wb : Wf;
        int g = gx * 256 + tid;
        float acc0 = 0.f, acc1 = 0.f, acc2 = 0.f, acc3 = 0.f;
#pragma unroll 4
        for (int d = 0; d < 512; ++d) {
            float w = W[(size_t)d * 2048 + g];
            acc0 = fmaf(embed[(size_t)(v0 + 0) * 512 + d], w, acc0);
            acc1 = fmaf(embed[(size_t)(v0 + 1) * 512 + d], w, acc1);
            acc2 = fmaf(embed[(size_t)(v0 + 2) * 512 + d], w, acc2);
            acc3 = fmaf(embed[(size_t)(v0 + 3) * 512 + d], w, acc3);
        }
        g_base[dir][v0 + 0][g] = acc0;
        g_base[dir][v0 + 1][g] = acc1;
        g_base[dir][v0 + 2][g] = acc2;
        g_base[dir][v0 + 3][g] = acc3;
    } else {
        // drop part: rows via warps
        unsigned row = ((unsigned)(bid - 1024) * 256u + (unsigned)tid) >> 5;
        int lane = tid & 31;
        uint2 kd = g_kd;
        int tok = tokens[row];
        const float* erow = &embed[(size_t)tok * 512];
        uint2* outp = &g_dropPack[(size_t)row * 128];
        unsigned count = 0;
#pragma unroll 4
        for (int it = 0; it < 16; ++it) {
            int d = it * 32 + lane;
            uint32_t bits = pbits(kd.x, kd.y, row * 512u + (unsigned)d);
            bool dropped = !(u01(bits) < 0.9f);
            unsigned m = __ballot_sync(0xffffffffu, dropped);
            if (dropped) {
                unsigned pos = count + __popc(m & ((1u << lane) - 1u));
                outp[pos] = make_uint2((unsigned)d, __float_as_uint(erow[d]));
            }
            count += __popc(m);
        }
        if (lane == 0) g_dropN[row] = count;
    }
}

// ---------------- K3: projection (base + sparse dropout correction) ----------------
#define CORR_SMEM (512 * 64 * 4)

__global__ void __launch_bounds__(256, 1) proj_corr_kernel(const int* __restrict__ tokens,
                                                           const float* __restrict__ Wf,
                                                           const float* __restrict__ Wb,
                                                           const float* __restrict__ bf,
                                                           const float* __restrict__ bb) {
    extern __shared__ float sW[];
    int dir = blockIdx.x >> 5;
    int slice = blockIdx.x & 31;
    int g0 = slice * 64;
    const float* W = dir ? Wb : Wf;
    const float* bias = dir ? bb : bf;
    float* pre = dir ? g_preB : g_preF;
    const float* base = &g_base[dir][0][0];
    int tid = threadIdx.x;

    for (int i = tid; i < 512 * 64; i += 256)
        sW[i] = W[(size_t)(i >> 6) * 2048 + g0 + (i & 63)];
    __syncthreads();

    int lane = tid & 31, w = tid >> 5;
    float2 bv = *(const float2*)&bias[g0 + lane * 2];
    int rEnd = blockIdx.y * 4096 + 4096;
    for (int r = blockIdx.y * 4096 + w; r < rEnd; r += 8) {
        int tok = tokens[r];
        unsigned n = g_dropN[r];
        const uint2* lst = &g_dropPack[(size_t)r * 128];
        float2 acc = *(const float2*)&base[(size_t)tok * 2048 + g0 + lane * 2];
        for (unsigned j0 = 0; j0 < n; j0 += 32) {
            uint2 e = make_uint2(0u, 0u);
            if (j0 + lane < n) e = __ldcg(&lst[j0 + lane]);
#pragma unroll
            for (int jj = 0; jj < 32; ++jj) {
                unsigned dx = __shfl_sync(0xffffffffu, e.x, jj);
                unsigned dv = __shfl_sync(0xffffffffu, e.y, jj);
                float val = __uint_as_float(dv);
                float2 wv = *(const float2*)&sW[dx * 64 + lane * 2];
                acc.x = fmaf(-val, wv.x, acc.x);
                acc.y = fmaf(-val, wv.y, acc.y);
            }
        }
        int b = r >> 10, t = r & 1023;
        float2 o;
        o.x = fmaf(acc.x, (1.0f / 0.9f), bv.x);
        o.y = fmaf(acc.y, (1.0f / 0.9f), bv.y);
        *(float2*)&pre[(((size_t)t * 64) + b) * 2048 + g0 + lane * 2] = o;
    }
}

// ---------------- K4: persistent bidirectional LSTM scan ----------------
#define LDB 520
#define SA_OFF   0
#define SBHI_OFF 139264
#define SBLO_OFF (SBHI_OFF + 32 * LDB * 2)
#define SD_OFF   (SBLO_OFF + 32 * LDB * 2)
#define LDD 40
#define SCAN_SMEM (SD_OFF + 128 * LDD * 4)
#define A_BLK_ELEMS (128 * LDAB)

__device__ __forceinline__ void wait_par(uint32_t bar, unsigned p) {
    asm volatile(
        "{\n\t.reg .pred P;\n\t"
        "WL_%=:\n\t"
        "mbarrier.try_wait.parity.acquire.cta.shared::cta.b64 P, [%0], %1, 0x989680;\n\t"
        "@P bra WD_%=;\n\t"
        "bra WL_%=;\n\t"
        "WD_%=:\n\t}"
        :: "r"(bar), "r"(p) : "memory");
}
__device__ __forceinline__ void tma_block(uint32_t dst, const unsigned char* src, uint32_t bar) {
    asm volatile("mbarrier.arrive.expect_tx.shared.b64 _, [%0], %1;"
                 :: "r"(bar), "r"(A_BLOCK_BYTES) : "memory");
    asm volatile("cp.async.bulk.shared::cta.global.mbarrier::complete_tx::bytes [%0], [%1], %2, [%3];"
                 :: "r"(dst), "l"(src), "r"(A_BLOCK_BYTES), "r"(bar) : "memory");
}

__global__ void __launch_bounds__(256, 1) scan_kernel(const int* __restrict__ lengths,
                                                      const float* __restrict__ Wf,
                                                      const float* __restrict__ Wb) {
    extern __shared__ unsigned char smem[];
    __nv_bfloat16* sA   = (__nv_bfloat16*)(smem + SA_OFF);
    __nv_bfloat16* sBhi = (__nv_bfloat16*)(smem + SBHI_OFF);
    __nv_bfloat16* sBlo = (__nv_bfloat16*)(smem + SBLO_OFF);
    float* sD  = (float*)(smem + SD_OFF);
    float* sD2 = (float*)(smem + SA_OFF);            // reuses block0 A region post-consumption
    __shared__ int sLen[64];
    __shared__ __align__(8) unsigned long long mbars[4];

    int dir = blockIdx.x >> 6, cta = blockIdx.x & 63, d0 = cta * 8;
    int tid = threadIdx.x, wid = tid >> 5, lane = tid & 31;
    const float* W = dir ? Wb : Wf;

    uint32_t sA_addr = (uint32_t)__cvta_generic_to_shared(sA);
    uint32_t bar[4];
#pragma unroll
    for (int j = 0; j < 4; ++j) bar[j] = (uint32_t)__cvta_generic_to_shared(&mbars[j]);
    if (tid < 4)
        asm volatile("mbarrier.init.shared.b64 [%0], 1;" :: "r"(bar[tid]) : "memory");

    for (int i = tid; i < 32 * 512; i += 256) {
        int n = i & 31, k = i >> 5;
        float w = W[(size_t)(512 + k) * 2048 + ((n >> 3) << 9) + d0 + (n & 7)];
        __nv_bfloat16 hi = __float2bfloat16(w);
        __nv_bfloat16 lo = __float2bfloat16(w - __bfloat162float(hi));
        sBhi[n * LDB + k] = hi;
        sBlo[n * LDB + k] = lo;
    }
    if (tid < 64) sLen[tid] = lengths[tid];
    __syncthreads();

    if (tid < 4) tma_block(sA_addr + (unsigned)tid * A_BLOCK_BYTES, g_hA[dir][0][tid], bar[tid]);

    int q = tid >> 6, b = tid & 63;
    int dd = q * 2, d = d0 + dd;
    float c0r = 0.f, c1r = 0.f;
    float hp0r = 0.f, hp1r = 0.f;
    const float* pre = dir ? g_preB : g_preF;
    int mg = wid & 3, nt = wid >> 2;
    bool isHiWarp = (mg < 2);
    int blk = cta >> 4;
    unsigned colw = (unsigned)(d & 127);
    size_t offH = (size_t)(b * LDAB + colw) * 2;
    size_t offL = (size_t)((b + 64) * LDAB + colw) * 2;
    unsigned p0 = (unsigned)(b * 512 + d);

    for (int s = 0; s < 1024; ++s) {
        int tx = dir ? (1023 - s) : s;
        unsigned par = (unsigned)(s & 1);

        size_t prow = ((size_t)tx * 64 + b) * 2048 + (size_t)d;
        float2 pxi = *(const float2*)&pre[prow];
        float2 pxg = *(const float2*)&pre[prow + 512];
        float2 pxf = *(const float2*)&pre[prow + 1024];
        float2 pxo = *(const float2*)&pre[prow + 1536];
        uint2 kz = __ldg(&g_kz[dir * 1024 + s]);
        bool kh0 = u01(pbits(kz.x, kz.y, p0)) < 0.1f;
        bool kh1 = u01(pbits(kz.x, kz.y, p0 + 1u)) < 0.1f;
        bool kc0 = u01(pbits(kz.x, kz.y, p0 + 32768u)) < 0.1f;
        bool kc1 = u01(pbits(kz.x, kz.y, p0 + 32769u)) < 0.1f;

        wmma::fragment<wmma::accumulator, 16, 16, 16, float> acc0, acc1, acc2, acc3;
        wmma::fill_fragment(acc0, 0.0f);
        wmma::fill_fragment(acc1, 0.0f);
        if (isHiWarp) { wmma::fill_fragment(acc2, 0.0f); wmma::fill_fragment(acc3, 0.0f); }
        const __nv_bfloat16* bh_base = sBhi + nt * 16 * LDB;
        const __nv_bfloat16* bl_base = sBlo + nt * 16 * LDB;

#pragma unroll 1
        for (int bk = 0; bk < 4; ++bk) {
            wait_par(bar[bk], par);
            const __nv_bfloat16* a0p = sA + bk * A_BLK_ELEMS + (mg * 32) * LDAB;
            const __nv_bfloat16* a1p = a0p + 16 * LDAB;
            const __nv_bfloat16* bhp = bh_base + bk * 128;
            const __nv_bfloat16* blp = bl_base + bk * 128;
#pragma unroll 4
            for (int kt = 0; kt < 8; ++kt) {
                wmma::fragment<wmma::matrix_a, 16, 16, 16, __nv_bfloat16, wmma::row_major> a0f, a1f;
                wmma::fragment<wmma::matrix_b, 16, 16, 16, __nv_bfloat16, wmma::col_major> bhf;
                wmma::load_matrix_sync(a0f, a0p + kt * 16, LDAB);
                wmma::load_matrix_sync(a1f, a1p + kt * 16, LDAB);
                wmma::load_matrix_sync(bhf, bhp + kt * 16, LDB);
                wmma::mma_sync(acc0, a0f, bhf, acc0);
                wmma::mma_sync(acc1, a1f, bhf, acc1);
                if (isHiWarp) {
                    wmma::fragment<wmma::matrix_b, 16, 16, 16, __nv_bfloat16, wmma::col_major> blf;
                    wmma::load_matrix_sync(blf, blp + kt * 16, LDB);
                    wmma::mma_sync(acc2, a0f, blf, acc2);
                    wmma::mma_sync(acc3, a1f, blf, acc3);
                }
            }
        }
        wmma::store_matrix_sync(sD + (mg * 2) * 16 * LDD + nt * 16, acc0, LDD, wmma::mem_row_major);
        wmma::store_matrix_sync(sD + (mg * 2 + 1) * 16 * LDD + nt * 16, acc1, LDD, wmma::mem_row_major);
        __syncthreads();
        if (isHiWarp) {
            wmma::store_matrix_sync(sD2 + (mg * 2) * 16 * LDD + nt * 16, acc2, LDD, wmma::mem_row_major);
            wmma::store_matrix_sync(sD2 + (mg * 2 + 1) * 16 * LDD + nt * 16, acc3, LDD, wmma::mem_row_major);
        }
        __syncthreads();

        if (dir && (1023 - s) < sLen[b] - 1) { c0r = 0.f; c1r = 0.f; }
        const float* dt = &sD[b * LDD];
        const float* db = &sD[(b + 64) * LDD];
        const float* d2 = &sD2[b * LDD];
        float a_i0 = dt[dd] + db[dd] + d2[dd];
        float a_i1 = dt[dd + 1] + db[dd + 1] + d2[dd + 1];
        float a_g0 = dt[8 + dd] + db[8 + dd] + d2[8 + dd];
        float a_g1 = dt[9 + dd] + db[9 + dd] + d2[9 + dd];
        float a_f0 = dt[16 + dd] + db[16 + dd] + d2[16 + dd];
        float a_f1 = dt[17 + dd] + db[17 + dd] + d2[17 + dd];
        float a_o0 = dt[24 + dd] + db[24 + dd] + d2[24 + dd];
        float a_o1 = dt[25 + dd] + db[25 + dd] + d2[25 + dd];
        float f0 = sigm_fast(pxf.x + a_f0 + 1.f), f1 = sigm_fast(pxf.y + a_f1 + 1.f);
        float o0 = sigm_fast(pxo.x + a_o0), o1 = sigm_fast(pxo.y + a_o1);
        float cn0 = f0 * c0r + sigm_fast(pxi.x + a_i0) * tanh_fast(pxg.x + a_g0);
        float cn1 = f1 * c1r + sigm_fast(pxi.y + a_i1) * tanh_fast(pxg.y + a_g1);
        float hn0 = o0 * tanh_fast(cn0);
        float hn1 = o1 * tanh_fast(cn1);
        float ho0 = kh0 ? hp0r : hn0;
        float ho1 = kh1 ? hp1r : hn1;
        c0r = kc0 ? c0r : cn0;
        c1r = kc1 ? c1r : cn1;

        float w0 = ho0, w1 = ho1;
        if (dir && (1022 - s) < sLen[b] - 1) { w0 = 0.f; w1 = 0.f; }
        hp0r = w0; hp1r = w1;
        __nv_bfloat16 h0 = __float2bfloat16(w0), h1 = __float2bfloat16(w1);
        __nv_bfloat16 l0 = __float2bfloat16(w0 - __bfloat162float(h0));
        __nv_bfloat16 l1 = __float2bfloat16(w1 - __bfloat162float(h1));
        unsigned char* hw = g_hA[dir][(s + 1) & 1][blk];
        uint32_t hv = (uint32_t)__bfloat16_as_ushort(h0) | ((uint32_t)__bfloat16_as_ushort(h1) << 16);
        uint32_t lv = (uint32_t)__bfloat16_as_ushort(l0) | ((uint32_t)__bfloat16_as_ushort(l1) << 16);
        __stcg((uint32_t*)(hw + offH), hv);
        __stcg((uint32_t*)(hw + offL), lv);

        // coalesced time-major output: g_outS[t][dir][d][b] (lane-consecutive b)
        float* os = &g_outS[(((size_t)tx * 2 + dir) * 512 + d) * 64 + b];

        __syncthreads();
        if (s < 1023) {
            if (tid == 0) {
                __threadfence();
                *(volatile unsigned*)&g_flag[dir][cta].v = (unsigned)(s + 1);
            }
            os[0] = ho0;
            os[64] = ho1;
            if (wid < 4) {
                if (lane < 16) {
                    volatile unsigned* f = &g_flag[dir][wid * 16 + lane].v;
                    while (*f < (unsigned)(s + 1)) __nanosleep(64);
                }
                __syncwarp();
                if (lane == 0)
                    tma_block(sA_addr + (unsigned)wid * A_BLOCK_BYTES,
                              g_hA[dir][(s + 1) & 1][wid], bar[wid]);
            }
        } else {
            os[0] = ho0;
            os[64] = ho1;
        }
    }
}

// ---------------- K5: transpose g_outS -> out [b][l][2*512] ----------------
__global__ void __launch_bounds__(256) transpose_kernel(float* __restrict__ out) {
    // block: (l, dir, dblk of 32 dims). Read coalesced (64 b), write coalesced (32 d).
    __shared__ float sT[32][65];
    unsigned bid = blockIdx.x;
    int dblk = bid & 15;           // 16 x 32 dims
    int dir = (bid >> 4) & 1;
    int l = bid >> 5;              // 0..1023
    const float* src = &g_outS[(((size_t)l * 2 + dir) * 512 + dblk * 32) * 64];
    int tid = threadIdx.x;
#pragma unroll
    for (int i = 0; i < 8; ++i) {
        int idx = tid + i * 256;            // 0..2047
        int r = idx >> 6, c = idx & 63;
        sT[r][c] = src[idx];
    }
    __syncthreads();
#pragma unroll
    for (int i = 0; i < 8; ++i) {
        int idx = tid + i * 256;
        int b = idx >> 5, r = idx & 31;     // b 0..63, r 0..31
        out[((size_t)b * 1024 + l) * 1024 + dir * 512 + dblk * 32 + r] = sT[r][b];
    }
}

// ---------------- launch ----------------
extern "C" void kernel_launch(void* const* d_in, const int* in_sizes, int n_in,
                              void* d_out, int out_size) {
    (void)in_sizes; (void)n_in; (void)out_size;
    const int*   tokens  = (const int*)d_in[0];
    const int*   lengths = (const int*)d_in[1];
    const float* embed   = (const float*)d_in[2];
    const float* Wf      = (const float*)d_in[3];
    const float* bf      = (const float*)d_in[4];
    const float* Wb      = (const float*)d_in[5];
    const float* bb      = (const float*)d_in[6];
    float* out = (float*)d_out;

    cudaFuncSetAttribute(scan_kernel, cudaFuncAttributeMaxDynamicSharedMemorySize, SCAN_SMEM);
    cudaFuncSetAttribute(proj_corr_kernel, cudaFuncAttributeMaxDynamicSharedMemorySize, CORR_SMEM);

    setup_kernel<<<64, 256>>>();
    basedrop_kernel<<<1024 + 8192, 256>>>(tokens, embed, Wf, Wb);
    proj_corr_kernel<<<dim3(64, 16), 256, CORR_SMEM>>>(tokens, Wf, Wb, bf, bb);
    scan_kernel<<<128, 256, SCAN_SMEM>>>(lengths, Wf, Wb);
    transpose_kernel<<<1024 * 2 * 16, 256>>>(out);
}